// round 3
// baseline (speedup 1.0000x reference)
#include <cuda_runtime.h>

#define D_MODEL 1024
#define NHEAD   16
#define HD      64
#define SEQ     2048
#define NB      4
#define M_TOTAL (NB * SEQ)   // 8192

// Scratch (allocation-free rule: __device__ globals)
__device__ float g_q[(size_t)M_TOTAL * D_MODEL];
__device__ float g_k[(size_t)M_TOTAL * D_MODEL];
__device__ float g_v[(size_t)M_TOTAL * D_MODEL];
__device__ float g_att[(size_t)M_TOTAL * D_MODEL];

// ---------------------------------------------------------------------------
// GEMM: C[M,N] = A[M,K] * B[N,K]^T   (both operands K-contiguous)
// 128x128 block tile, BK=8, 256 threads, 8x8 register tile, double-buffered.
// head_layout=1 remaps output n=(h,hd), m=(b,s) -> [B,H,S,Hd] for attention.
// ---------------------------------------------------------------------------
__global__ __launch_bounds__(256, 2)
void gemm_tn(const float* __restrict__ A, const float* __restrict__ Bw,
             float* __restrict__ C, int head_layout)
{
    const int K = D_MODEL;
    __shared__ float As[2][8][128];
    __shared__ float Bs[2][8][128];

    const int m0 = blockIdx.y << 7;
    const int n0 = blockIdx.x << 7;
    const int tid = threadIdx.x;
    const int lrow = tid >> 1;          // 0..127
    const int lc   = (tid & 1) << 2;    // 0 or 4

    const float* Ap = A  + (size_t)(m0 + lrow) * K + lc;
    const float* Bp = Bw + (size_t)(n0 + lrow) * K + lc;

    float4 av = *(const float4*)Ap;
    float4 bv = *(const float4*)Bp;
    As[0][lc + 0][lrow] = av.x; As[0][lc + 1][lrow] = av.y;
    As[0][lc + 2][lrow] = av.z; As[0][lc + 3][lrow] = av.w;
    Bs[0][lc + 0][lrow] = bv.x; Bs[0][lc + 1][lrow] = bv.y;
    Bs[0][lc + 2][lrow] = bv.z; Bs[0][lc + 3][lrow] = bv.w;
    __syncthreads();

    const int tx = tid & 15;
    const int ty = tid >> 4;

    float acc[8][8];
#pragma unroll
    for (int i = 0; i < 8; ++i)
#pragma unroll
        for (int j = 0; j < 8; ++j) acc[i][j] = 0.f;

    const int NK = K >> 3;  // 128 k-tiles
    for (int t = 0; t < NK; ++t) {
        const int cur = t & 1;
        if (t + 1 < NK) {
            av = *(const float4*)(Ap + (t + 1) * 8);
            bv = *(const float4*)(Bp + (t + 1) * 8);
        }
#pragma unroll
        for (int kk = 0; kk < 8; ++kk) {
            float4 a0 = *(const float4*)&As[cur][kk][ty * 8];
            float4 a1 = *(const float4*)&As[cur][kk][ty * 8 + 4];
            float4 b0 = *(const float4*)&Bs[cur][kk][tx * 8];
            float4 b1 = *(const float4*)&Bs[cur][kk][tx * 8 + 4];
            float a[8]  = {a0.x, a0.y, a0.z, a0.w, a1.x, a1.y, a1.z, a1.w};
            float bb[8] = {b0.x, b0.y, b0.z, b0.w, b1.x, b1.y, b1.z, b1.w};
#pragma unroll
            for (int i = 0; i < 8; ++i)
#pragma unroll
                for (int j = 0; j < 8; ++j)
                    acc[i][j] += a[i] * bb[j];
        }
        if (t + 1 < NK) {
            const int nxt = cur ^ 1;
            As[nxt][lc + 0][lrow] = av.x; As[nxt][lc + 1][lrow] = av.y;
            As[nxt][lc + 2][lrow] = av.z; As[nxt][lc + 3][lrow] = av.w;
            Bs[nxt][lc + 0][lrow] = bv.x; Bs[nxt][lc + 1][lrow] = bv.y;
            Bs[nxt][lc + 2][lrow] = bv.z; Bs[nxt][lc + 3][lrow] = bv.w;
        }
        __syncthreads();
    }

#pragma unroll
    for (int i = 0; i < 8; ++i) {
        const int m = m0 + ty * 8 + i;
#pragma unroll
        for (int j4 = 0; j4 < 8; j4 += 4) {
            const int n = n0 + tx * 8 + j4;
            float4 r = make_float4(acc[i][j4], acc[i][j4 + 1],
                                   acc[i][j4 + 2], acc[i][j4 + 3]);
            if (head_layout) {
                const int b = m >> 11, s = m & (SEQ - 1);
                const int h = n >> 6,  hd = n & 63;
                *(float4*)&C[((size_t)((b << 4) + h) * SEQ + s) * HD + hd] = r;
            } else {
                *(float4*)&C[(size_t)m * D_MODEL + n] = r;
            }
        }
    }
}

// ---------------------------------------------------------------------------
// Flash attention, causal. BQ = BK = 64, Hd = 64, 256 threads.
// Smem tiles transposed (Qt[d][r], Kt[d][c], Pt[c][r]) so score + PV inner
// loops are LDS.128-fed and FMA-bound. Output in [B,S,D] layout.
// ---------------------------------------------------------------------------
#define SQS 68   // stride for Qt/Kt/Vs (float4-aligned, conflict-free reads)
#define SPS 65   // stride for Pt (scalar reads, low-conflict stores)
#define NEG_BIG (-1e30f)

__global__ __launch_bounds__(256)
void attn_kernel(const float* __restrict__ q, const float* __restrict__ k,
                 const float* __restrict__ v, float* __restrict__ out)
{
    extern __shared__ float sm[];
    float* Qt = sm;                 // [64][SQS] transposed: Qt[d*SQS + r]
    float* Kt = Qt + 64 * SQS;      // [64][SQS] transposed: Kt[d*SQS + c]
    float* Vs = Kt + 64 * SQS;      // [64][SQS] row-major:  Vs[c*SQS + d]
    float* Pt = Vs + 64 * SQS;      // [64][SPS] transposed: Pt[c*SPS + r]

    const int bh = blockIdx.y;
    const int qb = blockIdx.x;
    const int q0 = qb << 6;
    const float* qbase = q + (size_t)bh * SEQ * HD;
    const float* kbase = k + (size_t)bh * SEQ * HD;
    const float* vbase = v + (size_t)bh * SEQ * HD;

    const int tid = threadIdx.x;
    const int ldr = tid >> 2;          // row 0..63
    const int ldc = (tid & 3) << 4;    // 0,16,32,48

    // Load Q tile transposed, pre-scaled by 1/sqrt(64)
    {
        const float* src = qbase + (size_t)(q0 + ldr) * HD + ldc;
#pragma unroll
        for (int u = 0; u < 4; ++u) {
            float4 t4 = *(const float4*)(src + u * 4);
            int d = ldc + u * 4;
            Qt[(d + 0) * SQS + ldr] = t4.x * 0.125f;
            Qt[(d + 1) * SQS + ldr] = t4.y * 0.125f;
            Qt[(d + 2) * SQS + ldr] = t4.z * 0.125f;
            Qt[(d + 3) * SQS + ldr] = t4.w * 0.125f;
        }
    }

    const int tx = tid & 15;   // 4-wide column block
    const int ty = tid >> 4;   // 4-wide row block

    float m_i[4] = {NEG_BIG, NEG_BIG, NEG_BIG, NEG_BIG};
    float l_i[4] = {0.f, 0.f, 0.f, 0.f};
    float o[4][4] = {};

    const int nkb = qb + 1;  // causal: only key blocks <= query block
    for (int kb = 0; kb < nkb; ++kb) {
        __syncthreads();  // previous iter's Pt/Vs reads complete
        {
            const float* ks = kbase + (size_t)((kb << 6) + ldr) * HD + ldc;
            const float* vs = vbase + (size_t)((kb << 6) + ldr) * HD + ldc;
#pragma unroll
            for (int u = 0; u < 4; ++u) {
                float4 t4 = *(const float4*)(ks + u * 4);
                int d = ldc + u * 4;
                Kt[(d + 0) * SQS + ldr] = t4.x;
                Kt[(d + 1) * SQS + ldr] = t4.y;
                Kt[(d + 2) * SQS + ldr] = t4.z;
                Kt[(d + 3) * SQS + ldr] = t4.w;
                float4 v4 = *(const float4*)(vs + u * 4);
                *(float4*)&Vs[ldr * SQS + d] = v4;
            }
        }
        __syncthreads();

        // Scores: s[i][j] = sum_d Qt[d][ty*4+i] * Kt[d][tx*4+j]
        float s[4][4] = {};
#pragma unroll 4
        for (int d = 0; d < 64; ++d) {
            float4 qa = *(const float4*)&Qt[d * SQS + (ty << 2)];
            float4 ka = *(const float4*)&Kt[d * SQS + (tx << 2)];
            float aa[4] = {qa.x, qa.y, qa.z, qa.w};
            float bb[4] = {ka.x, ka.y, ka.z, ka.w};
#pragma unroll
            for (int i = 0; i < 4; ++i)
#pragma unroll
                for (int j = 0; j < 4; ++j)
                    s[i][j] += aa[i] * bb[j];
        }

        if (kb == qb) {  // diagonal block: mask c > r
#pragma unroll
            for (int i = 0; i < 4; ++i)
#pragma unroll
                for (int j = 0; j < 4; ++j)
                    if ((tx << 2) + j > (ty << 2) + i) s[i][j] = NEG_BIG;
        }

        // Online softmax per row (16 threads of same ty share a row group)
#pragma unroll
        for (int i = 0; i < 4; ++i) {
            float mx = fmaxf(fmaxf(s[i][0], s[i][1]), fmaxf(s[i][2], s[i][3]));
#pragma unroll
            for (int off = 8; off > 0; off >>= 1)
                mx = fmaxf(mx, __shfl_xor_sync(0xffffffffu, mx, off));
            float mnew = fmaxf(m_i[i], mx);
            float corr = __expf(m_i[i] - mnew);
            float rs = 0.f;
#pragma unroll
            for (int j = 0; j < 4; ++j) {
                float p = __expf(s[i][j] - mnew);
                rs += p;
                Pt[((tx << 2) + j) * SPS + (ty << 2) + i] = p;
            }
#pragma unroll
            for (int off = 8; off > 0; off >>= 1)
                rs += __shfl_xor_sync(0xffffffffu, rs, off);
            m_i[i] = mnew;
            l_i[i] = l_i[i] * corr + rs;
#pragma unroll
            for (int j = 0; j < 4; ++j) o[i][j] *= corr;
        }
        __syncthreads();

        // PV: o[i][j] += sum_c Pt[c][ty*4+i] * Vs[c][tx*4+j]
#pragma unroll 2
        for (int c = 0; c < 64; ++c) {
            float4 vv = *(const float4*)&Vs[c * SQS + (tx << 2)];
            float p0 = Pt[c * SPS + (ty << 2) + 0];
            float p1 = Pt[c * SPS + (ty << 2) + 1];
            float p2 = Pt[c * SPS + (ty << 2) + 2];
            float p3 = Pt[c * SPS + (ty << 2) + 3];
            o[0][0] += p0 * vv.x; o[0][1] += p0 * vv.y; o[0][2] += p0 * vv.z; o[0][3] += p0 * vv.w;
            o[1][0] += p1 * vv.x; o[1][1] += p1 * vv.y; o[1][2] += p1 * vv.z; o[1][3] += p1 * vv.w;
            o[2][0] += p2 * vv.x; o[2][1] += p2 * vv.y; o[2][2] += p2 * vv.z; o[2][3] += p2 * vv.w;
            o[3][0] += p3 * vv.x; o[3][1] += p3 * vv.y; o[3][2] += p3 * vv.z; o[3][3] += p3 * vv.w;
        }
    }

    // Write output in [B,S,D] layout (d = h*64 + hd) for the O projection
    const int b = bh >> 4, h = bh & 15;
#pragma unroll
    for (int i = 0; i < 4; ++i) {
        const int r = (ty << 2) + i;
        const float inv = 1.0f / l_i[i];
        float4 res = make_float4(o[i][0] * inv, o[i][1] * inv,
                                 o[i][2] * inv, o[i][3] * inv);
        *(float4*)&out[((size_t)(b * SEQ) + q0 + r) * D_MODEL + h * HD + (tx << 2)] = res;
    }
}

// ---------------------------------------------------------------------------
extern "C" void kernel_launch(void* const* d_in, const int* in_sizes, int n_in,
                              void* d_out, int out_size)
{
    const float* x  = (const float*)d_in[0];
    const float* wq = (const float*)d_in[1];
    const float* wk = (const float*)d_in[2];
    const float* wv = (const float*)d_in[3];
    const float* wo = (const float*)d_in[4];
    float* out = (float*)d_out;

    float *q, *k, *v, *att;
    cudaGetSymbolAddress((void**)&q,   g_q);
    cudaGetSymbolAddress((void**)&k,   g_k);
    cudaGetSymbolAddress((void**)&v,   g_v);
    cudaGetSymbolAddress((void**)&att, g_att);

    dim3 gg(D_MODEL / 128, M_TOTAL / 128);  // (8, 64)
    gemm_tn<<<gg, 256>>>(x, wq, q, 1);
    gemm_tn<<<gg, 256>>>(x, wk, k, 1);
    gemm_tn<<<gg, 256>>>(x, wv, v, 1);

    const int smem_bytes = (64 * SQS * 3 + 64 * SPS) * (int)sizeof(float); // 68864
    cudaFuncSetAttribute((const void*)attn_kernel,
                         cudaFuncAttributeMaxDynamicSharedMemorySize, smem_bytes);
    attn_kernel<<<dim3(SEQ / 64, NB * NHEAD), 256, smem_bytes>>>(q, k, v, att);

    gemm_tn<<<gg, 256>>>(att, wo, out, 0);
}

// round 4
// speedup vs baseline: 2.1964x; 2.1964x over previous
#include <cuda_runtime.h>

#define D_MODEL 1024
#define NHEAD   16
#define HD      64
#define SEQ     2048
#define NB      4
#define M_TOTAL (NB * SEQ)   // 8192

// Scratch (allocation-free rule: __device__ globals)
__device__ float g_q[(size_t)M_TOTAL * D_MODEL];
__device__ float g_k[(size_t)M_TOTAL * D_MODEL];
__device__ float g_v[(size_t)M_TOTAL * D_MODEL];
__device__ float g_att[(size_t)M_TOTAL * D_MODEL];

// fp32 -> tf32 with round-to-nearest (unbiased; truncation would bias ~1e-3 over K=1024)
__device__ __forceinline__ unsigned f2tf(float x) {
    unsigned u;
    asm("cvt.rna.tf32.f32 %0, %1;" : "=r"(u) : "f"(x));
    return u;
}

// m16n8k8 tf32 mma. Fragment mapping (g = lane>>2, tg = lane&3):
//   A: a0=(g,tg) a1=(g+8,tg) a2=(g,tg+4) a3=(g+8,tg+4)
//   B: b0=(k=tg,n=g) b1=(k=tg+4,n=g)
//   C: c0=(g,2tg) c1=(g,2tg+1) c2=(g+8,2tg) c3=(g+8,2tg+1)
__device__ __forceinline__ void mma8(float c[4],
                                     unsigned a0, unsigned a1, unsigned a2, unsigned a3,
                                     unsigned b0, unsigned b1) {
    asm volatile(
        "mma.sync.aligned.m16n8k8.row.col.f32.tf32.tf32.f32 "
        "{%0,%1,%2,%3}, {%4,%5,%6,%7}, {%8,%9}, {%0,%1,%2,%3};"
        : "+f"(c[0]), "+f"(c[1]), "+f"(c[2]), "+f"(c[3])
        : "r"(a0), "r"(a1), "r"(a2), "r"(a3), "r"(b0), "r"(b1));
}

// ---------------------------------------------------------------------------
// GEMM: C[M,N] = A[M,K] * B[N,K]^T, tf32 tensor cores.
// 128x128 block, BK=16, 256 threads, 8 warps as 2x4 (warp tile 64x32),
// double-buffered smem, stride 20 (== 20 mod 32 -> conflict-free frag loads).
// ---------------------------------------------------------------------------
#define GBK 16
#define GSTR 20

__global__ __launch_bounds__(256, 2)
void gemm_tf32(const float* __restrict__ A, const float* __restrict__ Bw,
               float* __restrict__ C, int head_layout)
{
    __shared__ __align__(16) unsigned As[2][128][GSTR];
    __shared__ __align__(16) unsigned Bs[2][128][GSTR];
    const int K = D_MODEL;

    const int m0 = blockIdx.y << 7;
    const int n0 = blockIdx.x << 7;
    const int tid = threadIdx.x;
    const int lr = tid >> 1;        // 0..127
    const int lc = tid & 1;         // k-half: cols [0..7] or [8..15]

    const float* Ap = A  + (size_t)(m0 + lr) * K + lc * 8;
    const float* Bp = Bw + (size_t)(n0 + lr) * K + lc * 8;

    float4 a4[2], b4[2];
    a4[0] = *(const float4*)(Ap);     a4[1] = *(const float4*)(Ap + 4);
    b4[0] = *(const float4*)(Bp);     b4[1] = *(const float4*)(Bp + 4);

#define STORE_TILES(buf)                                                        \
    do {                                                                        \
        _Pragma("unroll")                                                       \
        for (int u = 0; u < 2; ++u) {                                           \
            uint4 ua = make_uint4(f2tf(a4[u].x), f2tf(a4[u].y),                 \
                                  f2tf(a4[u].z), f2tf(a4[u].w));                \
            *(uint4*)&As[buf][lr][lc * 8 + u * 4] = ua;                         \
            uint4 ub = make_uint4(f2tf(b4[u].x), f2tf(b4[u].y),                 \
                                  f2tf(b4[u].z), f2tf(b4[u].w));                \
            *(uint4*)&Bs[buf][lr][lc * 8 + u * 4] = ub;                         \
        }                                                                       \
    } while (0)

    STORE_TILES(0);
    __syncthreads();

    const int warp = tid >> 5, lane = tid & 31;
    const int wm = warp >> 2, wn = warp & 3;   // 2 x 4 warp grid
    const int g = lane >> 2, tg = lane & 3;

    float acc[4][4][4] = {};

    const int NK = K / GBK;  // 64
    for (int t = 0; t < NK; ++t) {
        const int cur = t & 1;
        if (t + 1 < NK) {
            a4[0] = *(const float4*)(Ap + (t + 1) * GBK);
            a4[1] = *(const float4*)(Ap + (t + 1) * GBK + 4);
            b4[0] = *(const float4*)(Bp + (t + 1) * GBK);
            b4[1] = *(const float4*)(Bp + (t + 1) * GBK + 4);
        }
#pragma unroll
        for (int ks = 0; ks < 2; ++ks) {
            const int k0 = ks * 8;
            unsigned af[4][4];
#pragma unroll
            for (int mt = 0; mt < 4; ++mt) {
                const int r = wm * 64 + mt * 16;
                af[mt][0] = As[cur][r + g][k0 + tg];
                af[mt][1] = As[cur][r + g + 8][k0 + tg];
                af[mt][2] = As[cur][r + g][k0 + tg + 4];
                af[mt][3] = As[cur][r + g + 8][k0 + tg + 4];
            }
#pragma unroll
            for (int nt = 0; nt < 4; ++nt) {
                const int cb = wn * 32 + nt * 8;
                unsigned b0 = Bs[cur][cb + g][k0 + tg];
                unsigned b1 = Bs[cur][cb + g][k0 + tg + 4];
#pragma unroll
                for (int mt = 0; mt < 4; ++mt)
                    mma8(acc[mt][nt], af[mt][0], af[mt][1], af[mt][2], af[mt][3], b0, b1);
            }
        }
        if (t + 1 < NK) {
            const int nxt = cur ^ 1;
            STORE_TILES(nxt);
        }
        __syncthreads();
    }

#pragma unroll
    for (int mt = 0; mt < 4; ++mt) {
#pragma unroll
        for (int nt = 0; nt < 4; ++nt) {
            const int r1 = m0 + wm * 64 + mt * 16 + g;
            const int r2 = r1 + 8;
            const int n  = n0 + wn * 32 + nt * 8 + tg * 2;
            float2 v1 = make_float2(acc[mt][nt][0], acc[mt][nt][1]);
            float2 v2 = make_float2(acc[mt][nt][2], acc[mt][nt][3]);
            if (head_layout) {
                const int h = n >> 6, hd = n & 63;
                const int b1 = r1 >> 11, s1 = r1 & (SEQ - 1);
                const int b2 = r2 >> 11, s2 = r2 & (SEQ - 1);
                *(float2*)&C[((size_t)((b1 << 4) + h) * SEQ + s1) * HD + hd] = v1;
                *(float2*)&C[((size_t)((b2 << 4) + h) * SEQ + s2) * HD + hd] = v2;
            } else {
                *(float2*)&C[(size_t)r1 * D_MODEL + n] = v1;
                *(float2*)&C[(size_t)r2 * D_MODEL + n] = v2;
            }
        }
    }
#undef STORE_TILES
}

// ---------------------------------------------------------------------------
// Flash attention, causal, tf32 tensor cores. BQ=BK=64, 128 threads (4 warps),
// warp tile = 16 query rows x full 64 keys (softmax reductions stay in a
// 4-lane shfl group). P round-trips smem per-warp (rows disjoint -> syncwarp).
// Smem stride 68 (== 4 mod 32 -> conflict-free fragment loads).
// ---------------------------------------------------------------------------
#define AST 68
#define NEG_BIG (-1e30f)

__global__ __launch_bounds__(128)
void attn_tf32(const float* __restrict__ q, const float* __restrict__ k,
               const float* __restrict__ v, float* __restrict__ out)
{
    extern __shared__ __align__(16) unsigned sm[];
    unsigned* Qs = sm;              // [64][AST]  Q row-major (r, d), pre-scaled
    unsigned* Ks = Qs + 64 * AST;   // [64][AST]  K row-major (c, d)
    unsigned* Vt = Ks + 64 * AST;   // [64][AST]  V transposed (d, c)
    unsigned* Ps = Vt + 64 * AST;   // [64][AST]  P row-major (r, c)

    const int bh = blockIdx.y;
    const int qb = blockIdx.x;
    const int q0 = qb << 6;
    const float* qbase = q + (size_t)bh * SEQ * HD;
    const float* kbase = k + (size_t)bh * SEQ * HD;
    const float* vbase = v + (size_t)bh * SEQ * HD;

    const int tid = threadIdx.x;
    const int warp = tid >> 5, lane = tid & 31;
    const int g = lane >> 2, tg = lane & 3;
    const int rq = warp * 16;          // this warp's query-row base (local)

    // Load Q tile (row-major), scaled by 1/sqrt(64), converted to tf32
    {
        const int r = tid >> 1, hf = tid & 1;
        const float* src = qbase + (size_t)(q0 + r) * HD + hf * 32;
#pragma unroll
        for (int u = 0; u < 8; ++u) {
            float4 t4 = *(const float4*)(src + u * 4);
            uint4 uu = make_uint4(f2tf(t4.x * 0.125f), f2tf(t4.y * 0.125f),
                                  f2tf(t4.z * 0.125f), f2tf(t4.w * 0.125f));
            *(uint4*)&Qs[r * AST + hf * 32 + u * 4] = uu;
        }
    }

    float m_i[2] = {NEG_BIG, NEG_BIG};
    float l_i[2] = {0.f, 0.f};
    float o[8][4] = {};

    const int nkb = qb + 1;  // causal
    for (int kb = 0; kb < nkb; ++kb) {
        __syncthreads();     // previous iter's Ks/Vt consumers done
        {
            const int r = tid >> 1, hf = tid & 1;
            const float* ks = kbase + (size_t)((kb << 6) + r) * HD + hf * 32;
            const float* vs = vbase + (size_t)((kb << 6) + r) * HD + hf * 32;
#pragma unroll
            for (int u = 0; u < 8; ++u) {
                float4 t4 = *(const float4*)(ks + u * 4);
                uint4 uu = make_uint4(f2tf(t4.x), f2tf(t4.y), f2tf(t4.z), f2tf(t4.w));
                *(uint4*)&Ks[r * AST + hf * 32 + u * 4] = uu;
                float4 v4 = *(const float4*)(vs + u * 4);
                const int d = hf * 32 + u * 4;
                Vt[(d + 0) * AST + r] = f2tf(v4.x);
                Vt[(d + 1) * AST + r] = f2tf(v4.y);
                Vt[(d + 2) * AST + r] = f2tf(v4.z);
                Vt[(d + 3) * AST + r] = f2tf(v4.w);
            }
        }
        __syncthreads();

        // Scores: S[16x64] = Q_warp[16x64] * K^T   (8 k-steps x 8 n-tiles)
        float s[8][4] = {};
#pragma unroll
        for (int ks = 0; ks < 8; ++ks) {
            const int k0 = ks * 8;
            unsigned a0 = Qs[(rq + g) * AST + k0 + tg];
            unsigned a1 = Qs[(rq + g + 8) * AST + k0 + tg];
            unsigned a2 = Qs[(rq + g) * AST + k0 + tg + 4];
            unsigned a3 = Qs[(rq + g + 8) * AST + k0 + tg + 4];
#pragma unroll
            for (int nt = 0; nt < 8; ++nt) {
                unsigned b0 = Ks[(nt * 8 + g) * AST + k0 + tg];
                unsigned b1 = Ks[(nt * 8 + g) * AST + k0 + tg + 4];
                mma8(s[nt], a0, a1, a2, a3, b0, b1);
            }
        }

        if (kb == qb) {  // diagonal block: mask col > row (local indices)
#pragma unroll
            for (int nt = 0; nt < 8; ++nt)
#pragma unroll
                for (int j = 0; j < 4; ++j) {
                    const int col = nt * 8 + tg * 2 + (j & 1);
                    const int row = rq + g + (j >> 1) * 8;
                    if (col > row) s[nt][j] = NEG_BIG;
                }
        }

        // Online softmax per row-half (rows g and g+8); 4-lane (tg) reduction
#pragma unroll
        for (int h2 = 0; h2 < 2; ++h2) {
            float mx = NEG_BIG;
#pragma unroll
            for (int nt = 0; nt < 8; ++nt)
                mx = fmaxf(mx, fmaxf(s[nt][2 * h2], s[nt][2 * h2 + 1]));
            mx = fmaxf(mx, __shfl_xor_sync(0xffffffffu, mx, 1));
            mx = fmaxf(mx, __shfl_xor_sync(0xffffffffu, mx, 2));
            const float mnew = fmaxf(m_i[h2], mx);
            const float corr = __expf(m_i[h2] - mnew);
            float rs = 0.f;
            const int prow = (rq + g + 8 * h2) * AST;
#pragma unroll
            for (int nt = 0; nt < 8; ++nt) {
                float p0 = __expf(s[nt][2 * h2] - mnew);
                float p1 = __expf(s[nt][2 * h2 + 1] - mnew);
                rs += p0 + p1;
                Ps[prow + nt * 8 + tg * 2]     = f2tf(p0);
                Ps[prow + nt * 8 + tg * 2 + 1] = f2tf(p1);
            }
            rs += __shfl_xor_sync(0xffffffffu, rs, 1);
            rs += __shfl_xor_sync(0xffffffffu, rs, 2);
            m_i[h2] = mnew;
            l_i[h2] = l_i[h2] * corr + rs;
#pragma unroll
            for (int nt = 0; nt < 8; ++nt) {
                o[nt][2 * h2]     *= corr;
                o[nt][2 * h2 + 1] *= corr;
            }
        }
        __syncwarp();   // Ps rows are per-warp private; warp-local fence suffices

        // PV: O[16x64] += P[16x64] * V[64x64]   (k = keys, n = head dim)
#pragma unroll
        for (int ks = 0; ks < 8; ++ks) {
            const int k0 = ks * 8;
            unsigned a0 = Ps[(rq + g) * AST + k0 + tg];
            unsigned a1 = Ps[(rq + g + 8) * AST + k0 + tg];
            unsigned a2 = Ps[(rq + g) * AST + k0 + tg + 4];
            unsigned a3 = Ps[(rq + g + 8) * AST + k0 + tg + 4];
#pragma unroll
            for (int nt = 0; nt < 8; ++nt) {
                unsigned b0 = Vt[(nt * 8 + g) * AST + k0 + tg];
                unsigned b1 = Vt[(nt * 8 + g) * AST + k0 + tg + 4];
                mma8(o[nt], a0, a1, a2, a3, b0, b1);
            }
        }
        __syncwarp();   // Ps reads done before next iter's stores
    }

    // Write output in [B,S,D] layout for the O projection
    const int b = bh >> 4, h = bh & 15;
#pragma unroll
    for (int h2 = 0; h2 < 2; ++h2) {
        const int r = q0 + rq + g + 8 * h2;
        const float inv = 1.0f / l_i[h2];
#pragma unroll
        for (int nt = 0; nt < 8; ++nt) {
            const int d = h * HD + nt * 8 + tg * 2;
            float2 res = make_float2(o[nt][2 * h2] * inv, o[nt][2 * h2 + 1] * inv);
            *(float2*)&out[((size_t)(b * SEQ) + r) * D_MODEL + d] = res;
        }
    }
}

// ---------------------------------------------------------------------------
extern "C" void kernel_launch(void* const* d_in, const int* in_sizes, int n_in,
                              void* d_out, int out_size)
{
    const float* x  = (const float*)d_in[0];
    const float* wq = (const float*)d_in[1];
    const float* wk = (const float*)d_in[2];
    const float* wv = (const float*)d_in[3];
    const float* wo = (const float*)d_in[4];
    float* out = (float*)d_out;

    float *q, *k, *v, *att;
    cudaGetSymbolAddress((void**)&q,   g_q);
    cudaGetSymbolAddress((void**)&k,   g_k);
    cudaGetSymbolAddress((void**)&v,   g_v);
    cudaGetSymbolAddress((void**)&att, g_att);

    dim3 gg(D_MODEL / 128, M_TOTAL / 128);  // (8, 64)
    gemm_tf32<<<gg, 256>>>(x, wq, q, 1);
    gemm_tf32<<<gg, 256>>>(x, wk, k, 1);
    gemm_tf32<<<gg, 256>>>(x, wv, v, 1);

    const int smem_bytes = 4 * 64 * AST * (int)sizeof(unsigned);  // 69632
    cudaFuncSetAttribute((const void*)attn_tf32,
                         cudaFuncAttributeMaxDynamicSharedMemorySize, smem_bytes);
    attn_tf32<<<dim3(SEQ / 64, NB * NHEAD), 128, smem_bytes>>>(q, k, v, att);

    gemm_tf32<<<gg, 256>>>(att, wo, out, 0);
}

// round 5
// speedup vs baseline: 3.2880x; 1.4970x over previous
#include <cuda_runtime.h>

#define D_MODEL 1024
#define NHEAD   16
#define HD      64
#define SEQ     2048
#define NB      4
#define M_TOTAL (NB * SEQ)   // 8192

// Scratch (allocation-free rule: __device__ globals)
__device__ float g_q  [(size_t)M_TOTAL * D_MODEL];
__device__ float g_k  [(size_t)M_TOTAL * D_MODEL];
__device__ float g_v  [(size_t)M_TOTAL * D_MODEL];
__device__ float g_att[(size_t)M_TOTAL * D_MODEL];
__device__ float g_xt [(size_t)M_TOTAL * D_MODEL];           // tf32-rounded x / att-free
__device__ float g_wc [4][(size_t)D_MODEL * D_MODEL];        // tf32-rounded weights

// fp32 -> tf32 round-to-nearest (unbiased)
__device__ __forceinline__ unsigned f2tf(float x) {
    unsigned u;
    asm("cvt.rna.tf32.f32 %0, %1;" : "=r"(u) : "f"(x));
    return u;
}
__device__ __forceinline__ float f2tf_f(float x) { return __uint_as_float(f2tf(x)); }

__device__ __forceinline__ void cp16(unsigned dst, const void* src) {
    asm volatile("cp.async.cg.shared.global [%0], [%1], 16;\n" :: "r"(dst), "l"(src));
}
#define CP_COMMIT() asm volatile("cp.async.commit_group;\n")
#define CP_WAIT(n)  asm volatile("cp.async.wait_group %0;\n" :: "n"(n))

// m16n8k8 tf32 mma. (g = lane>>2, tg = lane&3)
//   A: a0=(g,tg) a1=(g+8,tg) a2=(g,tg+4) a3=(g+8,tg+4)
//   B: b0=(k=tg,n=g) b1=(k=tg+4,n=g)
//   C: c0=(g,2tg) c1=(g,2tg+1) c2=(g+8,2tg) c3=(g+8,2tg+1)
__device__ __forceinline__ void mma8(float c[4],
                                     unsigned a0, unsigned a1, unsigned a2, unsigned a3,
                                     unsigned b0, unsigned b1) {
    asm volatile(
        "mma.sync.aligned.m16n8k8.row.col.f32.tf32.tf32.f32 "
        "{%0,%1,%2,%3}, {%4,%5,%6,%7}, {%8,%9}, {%0,%1,%2,%3};"
        : "+f"(c[0]), "+f"(c[1]), "+f"(c[2]), "+f"(c[3])
        : "r"(a0), "r"(a1), "r"(a2), "r"(a3), "r"(b0), "r"(b1));
}

// ---------------------------------------------------------------------------
// Prepass: elementwise tf32 rounding (n multiple of 4)
// ---------------------------------------------------------------------------
__global__ void cvt_rna_kernel(const float* __restrict__ src, float* __restrict__ dst, int n)
{
    int i = (blockIdx.x * blockDim.x + threadIdx.x) * 4;
    if (i < n) {
        float4 v = *(const float4*)(src + i);
        v.x = f2tf_f(v.x); v.y = f2tf_f(v.y); v.z = f2tf_f(v.z); v.w = f2tf_f(v.w);
        *(float4*)(dst + i) = v;
    }
}

// ---------------------------------------------------------------------------
// GEMM: C[M,N] = A[M,K] * B[N,K]^T. Inputs pre-rounded to tf32 in gmem.
// 128x128 block, BK=16, 256 threads, 8 warps 2x4 (warp tile 64x32),
// 4-stage cp.async pipeline. Smem stride 20 (conflict-free frag loads).
// ---------------------------------------------------------------------------
#define GBK  16
#define GSTR 20
#define GEMM_SMEM (4 * 2 * 128 * GSTR * 4)   // 81920 B

__global__ __launch_bounds__(256, 2)
void gemm_tf32(const float* __restrict__ A, const float* __restrict__ Bw,
               float* __restrict__ C, int head_layout, int cvt_out)
{
    extern __shared__ unsigned gsm[];
    unsigned* As = gsm;                      // [4][128*GSTR]
    unsigned* Bs = gsm + 4 * 128 * GSTR;
    const int K = D_MODEL;

    const int m0 = blockIdx.y << 7;
    const int n0 = blockIdx.x << 7;
    const int tid = threadIdx.x;
    const int lr = tid >> 2;            // 0..63
    const int lc = (tid & 3) << 2;      // 0,4,8,12

    const float* Ap = A  + (size_t)(m0 + lr) * K + lc;
    const float* Bp = Bw + (size_t)(n0 + lr) * K + lc;
    const unsigned sA = (unsigned)__cvta_generic_to_shared(As);
    const unsigned sB = (unsigned)__cvta_generic_to_shared(Bs);

#define G_ISSUE(t) do { const int st_ = (t) & 3;                                      \
    cp16(sA + (unsigned)(((st_ * 128 + lr)      * GSTR + lc) * 4), Ap + (t) * GBK);   \
    cp16(sA + (unsigned)(((st_ * 128 + lr + 64) * GSTR + lc) * 4), Ap + (t) * GBK + (size_t)64 * K); \
    cp16(sB + (unsigned)(((st_ * 128 + lr)      * GSTR + lc) * 4), Bp + (t) * GBK);   \
    cp16(sB + (unsigned)(((st_ * 128 + lr + 64) * GSTR + lc) * 4), Bp + (t) * GBK + (size_t)64 * K); \
    CP_COMMIT(); } while (0)

    G_ISSUE(0); G_ISSUE(1); G_ISSUE(2);

    const int warp = tid >> 5, lane = tid & 31;
    const int wm = warp >> 2, wn = warp & 3;
    const int g = lane >> 2, tg = lane & 3;

    float acc[4][4][4] = {};

    const int NK = K / GBK;  // 64
    for (int t = 0; t < NK; ++t) {
        CP_WAIT(2);          // tile t resident (own groups); barrier covers all threads
        __syncthreads();
        if (t + 3 < NK) G_ISSUE(t + 3);

        const unsigned* Ac = As + (t & 3) * 128 * GSTR;
        const unsigned* Bc = Bs + (t & 3) * 128 * GSTR;
#pragma unroll
        for (int ks = 0; ks < 2; ++ks) {
            const int k0 = ks * 8;
            unsigned af[4][4];
#pragma unroll
            for (int mt = 0; mt < 4; ++mt) {
                const int r = wm * 64 + mt * 16;
                af[mt][0] = Ac[(r + g)     * GSTR + k0 + tg];
                af[mt][1] = Ac[(r + g + 8) * GSTR + k0 + tg];
                af[mt][2] = Ac[(r + g)     * GSTR + k0 + tg + 4];
                af[mt][3] = Ac[(r + g + 8) * GSTR + k0 + tg + 4];
            }
#pragma unroll
            for (int nt = 0; nt < 4; ++nt) {
                const int cb = wn * 32 + nt * 8;
                unsigned b0 = Bc[(cb + g) * GSTR + k0 + tg];
                unsigned b1 = Bc[(cb + g) * GSTR + k0 + tg + 4];
#pragma unroll
                for (int mt = 0; mt < 4; ++mt)
                    mma8(acc[mt][nt], af[mt][0], af[mt][1], af[mt][2], af[mt][3], b0, b1);
            }
        }
        __syncthreads();     // stage (t&3) free for reuse by issue at iter t+1
    }

#pragma unroll
    for (int mt = 0; mt < 4; ++mt) {
#pragma unroll
        for (int nt = 0; nt < 4; ++nt) {
            const int r1 = m0 + wm * 64 + mt * 16 + g;
            const int r2 = r1 + 8;
            const int n  = n0 + wn * 32 + nt * 8 + tg * 2;
            float2 v1 = make_float2(acc[mt][nt][0], acc[mt][nt][1]);
            float2 v2 = make_float2(acc[mt][nt][2], acc[mt][nt][3]);
            if (cvt_out) {
                v1.x = f2tf_f(v1.x); v1.y = f2tf_f(v1.y);
                v2.x = f2tf_f(v2.x); v2.y = f2tf_f(v2.y);
            }
            if (head_layout) {
                const int h = n >> 6, hd = n & 63;
                const int b1 = r1 >> 11, s1 = r1 & (SEQ - 1);
                const int b2 = r2 >> 11, s2 = r2 & (SEQ - 1);
                *(float2*)&C[((size_t)((b1 << 4) + h) * SEQ + s1) * HD + hd] = v1;
                *(float2*)&C[((size_t)((b2 << 4) + h) * SEQ + s2) * HD + hd] = v2;
            } else {
                *(float2*)&C[(size_t)r1 * D_MODEL + n] = v1;
                *(float2*)&C[(size_t)r2 * D_MODEL + n] = v2;
            }
        }
    }
#undef G_ISSUE
}

// ---------------------------------------------------------------------------
// Flash attention, causal, tf32. BQ=128, BK=64, 256 threads (8 warps, each
// 16 query rows x 64 keys). K/V double-buffered via cp.async; V row-major
// (stride 72) so PV B-frags are conflict-free; P stays in registers and is
// repacked C-frag -> A-frag by warp shuffles (no Ps smem). q/k/v pre-rounded.
// ---------------------------------------------------------------------------
#define KST 68   // Qs/Ks stride: (4g+tg) mod 32 distinct -> conflict-free
#define VST 72   // Vs stride:    (8tg+g) mod 32 distinct -> conflict-free
#define ATTN_SMEM ((128 * KST + 2 * 64 * KST + 2 * 64 * VST) * 4)  // 106496 B
#define NEG_BIG (-1e30f)

__global__ __launch_bounds__(256, 2)
void attn_tf32(const float* __restrict__ q, const float* __restrict__ k,
               const float* __restrict__ v, float* __restrict__ att)
{
    extern __shared__ unsigned sm[];
    unsigned* Qs = sm;                       // [128][KST]
    unsigned* Ks = Qs + 128 * KST;           // [2][64][KST]
    unsigned* Vs = Ks + 2 * 64 * KST;        // [2][64][VST]
    const unsigned sK = (unsigned)__cvta_generic_to_shared(Ks);
    const unsigned sV = (unsigned)__cvta_generic_to_shared(Vs);

    const int bh = blockIdx.y;
    const int qb = gridDim.x - 1 - blockIdx.x;   // heavy blocks first
    const int q0 = qb << 7;
    const float* qbase = q + (size_t)bh * SEQ * HD;
    const float* kbase = k + (size_t)bh * SEQ * HD;
    const float* vbase = v + (size_t)bh * SEQ * HD;

    const int tid = threadIdx.x;
    const int warp = tid >> 5, lane = tid & 31;
    const int g = lane >> 2, tg = lane & 3;
    const int rq = warp * 16;

    // Stage Q (pre-rounded tf32 in gmem; *0.125 is exact, stays tf32)
#pragma unroll
    for (int i = 0; i < 8; ++i) {
        const int c = tid + i * 256;          // 2048 chunks of 4 floats
        const int row = c >> 4, col4 = (c & 15) << 2;
        float4 t4 = *(const float4*)(qbase + (size_t)(q0 + row) * HD + col4);
        uint4 u = make_uint4(__float_as_uint(t4.x * 0.125f), __float_as_uint(t4.y * 0.125f),
                             __float_as_uint(t4.z * 0.125f), __float_as_uint(t4.w * 0.125f));
        *(uint4*)&Qs[row * KST + col4] = u;
    }

    const int nkb = 2 * (qb + 1);

#define KV_ISSUE(kb) do { const int buf_ = (kb) & 1;                                   \
    _Pragma("unroll")                                                                  \
    for (int i_ = 0; i_ < 4; ++i_) {                                                   \
        const int c_ = tid + i_ * 256;                                                 \
        const int row_ = c_ >> 4, col_ = (c_ & 15) << 2;                               \
        cp16(sK + (unsigned)(((buf_ * 64 + row_) * KST + col_) * 4),                   \
             kbase + (size_t)(((kb) << 6) + row_) * HD + col_);                        \
        cp16(sV + (unsigned)(((buf_ * 64 + row_) * VST + col_) * 4),                   \
             vbase + (size_t)(((kb) << 6) + row_) * HD + col_);                        \
    }                                                                                  \
    CP_COMMIT(); } while (0)

    KV_ISSUE(0);

    float m_i[2] = {NEG_BIG, NEG_BIG};
    float l_i[2] = {0.f, 0.f};
    float o[8][4] = {};

    for (int kb = 0; kb < nkb; ++kb) {
        CP_WAIT(0);
        __syncthreads();                 // kb's K/V resident; prev readers done
        if (kb + 1 < nkb) KV_ISSUE(kb + 1);

        const bool active = ((kb << 6) <= q0 + rq + 15);  // warp has unmasked cols
        if (active) {
            const unsigned* Kc = Ks + (kb & 1) * 64 * KST;
            const unsigned* Vc = Vs + (kb & 1) * 64 * VST;

            // S[16x64] = Q_warp * K^T
            float s[8][4] = {};
#pragma unroll
            for (int ks = 0; ks < 8; ++ks) {
                const int k0 = ks * 8;
                unsigned a0 = Qs[(rq + g)     * KST + k0 + tg];
                unsigned a1 = Qs[(rq + g + 8) * KST + k0 + tg];
                unsigned a2 = Qs[(rq + g)     * KST + k0 + tg + 4];
                unsigned a3 = Qs[(rq + g + 8) * KST + k0 + tg + 4];
#pragma unroll
                for (int nt = 0; nt < 8; ++nt) {
                    unsigned b0 = Kc[(nt * 8 + g) * KST + k0 + tg];
                    unsigned b1 = Kc[(nt * 8 + g) * KST + k0 + tg + 4];
                    mma8(s[nt], a0, a1, a2, a3, b0, b1);
                }
            }

            if ((kb << 6) + 63 > q0 + rq) {   // block touches diagonal: mask
#pragma unroll
                for (int nt = 0; nt < 8; ++nt)
#pragma unroll
                    for (int j = 0; j < 4; ++j) {
                        const int col = (kb << 6) + nt * 8 + tg * 2 + (j & 1);
                        const int row = q0 + rq + g + 8 * (j >> 1);
                        if (col > row) s[nt][j] = NEG_BIG;
                    }
            }

            // Online softmax per row-half; p (tf32 bits) kept in registers
            unsigned pu[8][4];
#pragma unroll
            for (int h2 = 0; h2 < 2; ++h2) {
                float mx = NEG_BIG;
#pragma unroll
                for (int nt = 0; nt < 8; ++nt)
                    mx = fmaxf(mx, fmaxf(s[nt][2 * h2], s[nt][2 * h2 + 1]));
                mx = fmaxf(mx, __shfl_xor_sync(0xffffffffu, mx, 1));
                mx = fmaxf(mx, __shfl_xor_sync(0xffffffffu, mx, 2));
                const float mnew = fmaxf(m_i[h2], mx);
                const float corr = __expf(m_i[h2] - mnew);
                float rs = 0.f;
#pragma unroll
                for (int nt = 0; nt < 8; ++nt) {
                    float p0 = __expf(s[nt][2 * h2]     - mnew);
                    float p1 = __expf(s[nt][2 * h2 + 1] - mnew);
                    rs += p0 + p1;
                    pu[nt][2 * h2]     = f2tf(p0);
                    pu[nt][2 * h2 + 1] = f2tf(p1);
                }
                rs += __shfl_xor_sync(0xffffffffu, rs, 1);
                rs += __shfl_xor_sync(0xffffffffu, rs, 2);
                m_i[h2] = mnew;
                l_i[h2] = l_i[h2] * corr + rs;
#pragma unroll
                for (int nt = 0; nt < 8; ++nt) {
                    o[nt][2 * h2]     *= corr;
                    o[nt][2 * h2 + 1] *= corr;
                }
            }

            // PV: repack P C-frags -> A-frags via shuffles, B from row-major V
            const int srcA = (g << 2) | (tg >> 1);
            const int srcB = srcA + 2;
            const bool odd = (tg & 1);
#pragma unroll
            for (int ks = 0; ks < 8; ++ks) {
                const int k0 = ks * 8;
                unsigned u0 = __shfl_sync(0xffffffffu, pu[ks][0], srcA);
                unsigned u1 = __shfl_sync(0xffffffffu, pu[ks][1], srcA);
                unsigned u2 = __shfl_sync(0xffffffffu, pu[ks][2], srcA);
                unsigned u3 = __shfl_sync(0xffffffffu, pu[ks][3], srcA);
                unsigned w0 = __shfl_sync(0xffffffffu, pu[ks][0], srcB);
                unsigned w1 = __shfl_sync(0xffffffffu, pu[ks][1], srcB);
                unsigned w2 = __shfl_sync(0xffffffffu, pu[ks][2], srcB);
                unsigned w3 = __shfl_sync(0xffffffffu, pu[ks][3], srcB);
                unsigned a0 = odd ? u1 : u0;
                unsigned a1 = odd ? u3 : u2;
                unsigned a2 = odd ? w1 : w0;
                unsigned a3 = odd ? w3 : w2;
#pragma unroll
                for (int nt = 0; nt < 8; ++nt) {
                    unsigned b0 = Vc[(k0 + tg)     * VST + nt * 8 + g];
                    unsigned b1 = Vc[(k0 + tg + 4) * VST + nt * 8 + g];
                    mma8(o[nt], a0, a1, a2, a3, b0, b1);
                }
            }
        }
        __syncthreads();   // all reads of buffer (kb&1) done before its reuse
    }

    // Epilogue: [B,S,D] layout, tf32-rounded for the O projection
    const int b = bh >> 4, h = bh & 15;
#pragma unroll
    for (int h2 = 0; h2 < 2; ++h2) {
        const int r = q0 + rq + g + 8 * h2;
        const float inv = 1.0f / l_i[h2];
#pragma unroll
        for (int nt = 0; nt < 8; ++nt) {
            const int d = h * HD + nt * 8 + tg * 2;
            float2 res = make_float2(f2tf_f(o[nt][2 * h2] * inv),
                                     f2tf_f(o[nt][2 * h2 + 1] * inv));
            *(float2*)&att[((size_t)(b * SEQ) + r) * D_MODEL + d] = res;
        }
    }
#undef KV_ISSUE
}

// ---------------------------------------------------------------------------
extern "C" void kernel_launch(void* const* d_in, const int* in_sizes, int n_in,
                              void* d_out, int out_size)
{
    const float* x  = (const float*)d_in[0];
    const float* wq = (const float*)d_in[1];
    const float* wk = (const float*)d_in[2];
    const float* wv = (const float*)d_in[3];
    const float* wo = (const float*)d_in[4];
    float* out = (float*)d_out;

    float *q, *k, *v, *att, *xt, *wc;
    cudaGetSymbolAddress((void**)&q,   g_q);
    cudaGetSymbolAddress((void**)&k,   g_k);
    cudaGetSymbolAddress((void**)&v,   g_v);
    cudaGetSymbolAddress((void**)&att, g_att);
    cudaGetSymbolAddress((void**)&xt,  g_xt);
    cudaGetSymbolAddress((void**)&wc,  g_wc);

    const int NX = M_TOTAL * D_MODEL;      // 8388608
    const int NW = D_MODEL * D_MODEL;      // 1048576
    cvt_rna_kernel<<<NX / 4 / 256, 256>>>(x,  xt,            NX);
    cvt_rna_kernel<<<NW / 4 / 256, 256>>>(wq, wc + 0ul * NW, NW);
    cvt_rna_kernel<<<NW / 4 / 256, 256>>>(wk, wc + 1ul * NW, NW);
    cvt_rna_kernel<<<NW / 4 / 256, 256>>>(wv, wc + 2ul * NW, NW);
    cvt_rna_kernel<<<NW / 4 / 256, 256>>>(wo, wc + 3ul * NW, NW);

    cudaFuncSetAttribute((const void*)gemm_tf32,
                         cudaFuncAttributeMaxDynamicSharedMemorySize, GEMM_SMEM);
    cudaFuncSetAttribute((const void*)attn_tf32,
                         cudaFuncAttributeMaxDynamicSharedMemorySize, ATTN_SMEM);

    dim3 gg(D_MODEL / 128, M_TOTAL / 128);  // (8, 64)
    gemm_tf32<<<gg, 256, GEMM_SMEM>>>(xt, wc + 0ul * NW, q, 1, 1);
    gemm_tf32<<<gg, 256, GEMM_SMEM>>>(xt, wc + 1ul * NW, k, 1, 1);
    gemm_tf32<<<gg, 256, GEMM_SMEM>>>(xt, wc + 2ul * NW, v, 1, 1);

    attn_tf32<<<dim3(SEQ / 128, NB * NHEAD), 256, ATTN_SMEM>>>(q, k, v, att);

    gemm_tf32<<<gg, 256, GEMM_SMEM>>>(att, wc + 3ul * NW, out, 0, 0);
}

// round 6
// speedup vs baseline: 3.5355x; 1.0753x over previous
#include <cuda_runtime.h>

#define D_MODEL 1024
#define NHEAD   16
#define HD      64
#define SEQ     2048
#define NB      4
#define M_TOTAL (NB * SEQ)   // 8192
#define NW      (D_MODEL * D_MODEL)

// Scratch (allocation-free rule: __device__ globals)
__device__ float g_q  [(size_t)M_TOTAL * D_MODEL];   // [B,H,S,Hd], pre-scaled 0.125
__device__ float g_k  [(size_t)M_TOTAL * D_MODEL];   // [B,H,S,Hd]
__device__ float g_vt [(size_t)M_TOTAL * D_MODEL];   // [B,H,Hd,S]  (transposed V)
__device__ float g_att[(size_t)M_TOTAL * D_MODEL];   // [B,S,D]
__device__ float g_xt [(size_t)M_TOTAL * D_MODEL];   // tf32-rounded x
__device__ float g_wc [4][(size_t)NW];               // tf32-rounded weights q,k,v,o

// fp32 -> tf32 round-to-nearest (unbiased)
__device__ __forceinline__ unsigned f2tf(float x) {
    unsigned u;
    asm("cvt.rna.tf32.f32 %0, %1;" : "=r"(u) : "f"(x));
    return u;
}
__device__ __forceinline__ float f2tf_f(float x) { return __uint_as_float(f2tf(x)); }

__device__ __forceinline__ void cp16(unsigned dst, const void* src) {
    asm volatile("cp.async.cg.shared.global [%0], [%1], 16;\n" :: "r"(dst), "l"(src));
}
#define CP_COMMIT() asm volatile("cp.async.commit_group;\n")
#define CP_WAIT(n)  asm volatile("cp.async.wait_group %0;\n" :: "n"(n))

// ldmatrix.x4: tf32 fragments via b16 view (lane l -> row l/4, b32-col l%4 per matrix)
__device__ __forceinline__ void ldsm4(unsigned& r0, unsigned& r1, unsigned& r2, unsigned& r3,
                                      unsigned addr) {
    asm volatile("ldmatrix.sync.aligned.m8n8.x4.shared.b16 {%0,%1,%2,%3}, [%4];"
                 : "=r"(r0), "=r"(r1), "=r"(r2), "=r"(r3) : "r"(addr));
}

// m16n8k8 tf32 mma. (g = lane>>2, tg = lane&3)
__device__ __forceinline__ void mma8(float c[4],
                                     unsigned a0, unsigned a1, unsigned a2, unsigned a3,
                                     unsigned b0, unsigned b1) {
    asm volatile(
        "mma.sync.aligned.m16n8k8.row.col.f32.tf32.tf32.f32 "
        "{%0,%1,%2,%3}, {%4,%5,%6,%7}, {%8,%9}, {%0,%1,%2,%3};"
        : "+f"(c[0]), "+f"(c[1]), "+f"(c[2]), "+f"(c[3])
        : "r"(a0), "r"(a1), "r"(a2), "r"(a3), "r"(b0), "r"(b1));
}

// ---------------------------------------------------------------------------
// Prepass: tf32 rounding, 4 float4 per thread (MLP=4)
// ---------------------------------------------------------------------------
__global__ void cvt_rna_kernel(const float* __restrict__ src, float* __restrict__ dst, int n)
{
    const int base = (blockIdx.x * blockDim.x + threadIdx.x) * 16;
    if (base < n) {
        float4 a = *(const float4*)(src + base);
        float4 b = *(const float4*)(src + base + 4);
        float4 c = *(const float4*)(src + base + 8);
        float4 d = *(const float4*)(src + base + 12);
        a.x=f2tf_f(a.x); a.y=f2tf_f(a.y); a.z=f2tf_f(a.z); a.w=f2tf_f(a.w);
        b.x=f2tf_f(b.x); b.y=f2tf_f(b.y); b.z=f2tf_f(b.z); b.w=f2tf_f(b.w);
        c.x=f2tf_f(c.x); c.y=f2tf_f(c.y); c.z=f2tf_f(c.z); c.w=f2tf_f(c.w);
        d.x=f2tf_f(d.x); d.y=f2tf_f(d.y); d.z=f2tf_f(d.z); d.w=f2tf_f(d.w);
        *(float4*)(dst + base)      = a;
        *(float4*)(dst + base + 4)  = b;
        *(float4*)(dst + base + 8)  = c;
        *(float4*)(dst + base + 12) = d;
    }
}

// ---------------------------------------------------------------------------
// GEMM: C[M,N] = A[M,K] * W[N,K]^T. 128x128 tile, BK=16, 256 thr, 8 warps 2x4,
// 4-stage cp.async, ldmatrix fragments, ONE barrier per k-tile.
// mode: 0=q ([B,H,S,Hd], x0.125, cvt)  1=k ([B,H,S,Hd], cvt)
//       2=vt ([B,H,Hd,S], cvt)         3=out ([B,S,D], raw).  mode<0 -> blockIdx.z
// ---------------------------------------------------------------------------
#define GBK  16
#define GSTR 20
#define GEMM_SMEM (4 * 2 * 128 * GSTR * 4)   // 81920 B

__global__ __launch_bounds__(256, 2)
void gemm_tf32(const float* __restrict__ A, const float* __restrict__ W4,
               float* __restrict__ qp, float* __restrict__ kp,
               float* __restrict__ vtp, float* __restrict__ op, int mode_in)
{
    extern __shared__ unsigned gsm[];
    unsigned* As = gsm;                      // [4][128*GSTR]
    unsigned* Bs = gsm + 4 * 128 * GSTR;
    const int K = D_MODEL;
    const int mode = (mode_in < 0) ? (int)blockIdx.z : mode_in;
    const float* Bw = W4 + (size_t)mode * NW;

    const int m0 = blockIdx.y << 7;
    const int n0 = blockIdx.x << 7;
    const int tid = threadIdx.x;
    const int lr = tid >> 2;            // 0..63
    const int lc = (tid & 3) << 2;      // 0,4,8,12

    const float* Ap = A  + (size_t)(m0 + lr) * K + lc;
    const float* Bp = Bw + (size_t)(n0 + lr) * K + lc;
    const unsigned sA = (unsigned)__cvta_generic_to_shared(As);
    const unsigned sB = (unsigned)__cvta_generic_to_shared(Bs);

#define G_ISSUE(t) do { const int st_ = (t) & 3;                                      \
    cp16(sA + (unsigned)(((st_ * 128 + lr)      * GSTR + lc) * 4), Ap + (t) * GBK);   \
    cp16(sA + (unsigned)(((st_ * 128 + lr + 64) * GSTR + lc) * 4), Ap + (t) * GBK + (size_t)64 * K); \
    cp16(sB + (unsigned)(((st_ * 128 + lr)      * GSTR + lc) * 4), Bp + (t) * GBK);   \
    cp16(sB + (unsigned)(((st_ * 128 + lr + 64) * GSTR + lc) * 4), Bp + (t) * GBK + (size_t)64 * K); \
    CP_COMMIT(); } while (0)

    G_ISSUE(0); G_ISSUE(1); G_ISSUE(2);

    const int warp = tid >> 5, lane = tid & 31;
    const int wm = warp >> 2, wn = warp & 3;
    const int g = lane >> 2, tg = lane & 3;
    // ldmatrix per-lane offset: row = lane&15, col-words = (lane>>4)*4
    const unsigned lmg = (unsigned)((((lane & 15) * GSTR) + ((lane >> 4) << 2)) * 4);

    float acc[4][4][4] = {};

    const int NK = K / GBK;  // 64
    for (int t = 0; t < NK; ++t) {
        CP_WAIT(2);
        __syncthreads();                 // tile t fully resident for all threads
        if (t + 3 < NK) G_ISSUE(t + 3);  // writes stage (t-1)&3, proven reader-free

        const unsigned swA = sA + (unsigned)((t & 3) * 128 * GSTR * 4);
        const unsigned swB = sB + (unsigned)((t & 3) * 128 * GSTR * 4);
#pragma unroll
        for (int ks = 0; ks < 2; ++ks) {
            const int k0 = ks * 8;
            unsigned af[4][4];
#pragma unroll
            for (int mt = 0; mt < 4; ++mt)
                ldsm4(af[mt][0], af[mt][1], af[mt][2], af[mt][3],
                      swA + (unsigned)(((wm * 64 + mt * 16) * GSTR + k0) * 4) + lmg);
#pragma unroll
            for (int ntp = 0; ntp < 2; ++ntp) {
                unsigned b0e, b0o, b1e, b1o;
                ldsm4(b0e, b0o, b1e, b1o,
                      swB + (unsigned)(((wn * 32 + ntp * 16) * GSTR + k0) * 4) + lmg);
#pragma unroll
                for (int mt = 0; mt < 4; ++mt) {
                    mma8(acc[mt][2 * ntp],     af[mt][0], af[mt][1], af[mt][2], af[mt][3], b0e, b1e);
                    mma8(acc[mt][2 * ntp + 1], af[mt][0], af[mt][1], af[mt][2], af[mt][3], b0o, b1o);
                }
            }
        }
    }

    const float osc = (mode == 0) ? 0.125f : 1.0f;
    float* Cq = (mode == 0) ? qp : kp;   // modes 0/1 share the [B,H,S,Hd] path
#pragma unroll
    for (int mt = 0; mt < 4; ++mt) {
#pragma unroll
        for (int nt = 0; nt < 4; ++nt) {
            const int r1 = m0 + wm * 64 + mt * 16 + g;
            const int r2 = r1 + 8;
            const int n  = n0 + wn * 32 + nt * 8 + tg * 2;
            float v[4] = {acc[mt][nt][0], acc[mt][nt][1], acc[mt][nt][2], acc[mt][nt][3]};
            if (mode == 3) {
                *(float2*)&op[(size_t)r1 * D_MODEL + n] = make_float2(v[0], v[1]);
                *(float2*)&op[(size_t)r2 * D_MODEL + n] = make_float2(v[2], v[3]);
            } else {
                v[0] = f2tf_f(v[0] * osc); v[1] = f2tf_f(v[1] * osc);
                v[2] = f2tf_f(v[2] * osc); v[3] = f2tf_f(v[3] * osc);
                const int h = n >> 6, hd = n & 63;
                const int b1 = r1 >> 11, s1 = r1 & (SEQ - 1);
                const int b2 = r2 >> 11, s2 = r2 & (SEQ - 1);
                if (mode == 2) {  // transposed V: [B,H,Hd,S]
                    float* base = vtp + (size_t)((b1 << 4) + h) * HD * SEQ;
                    base[(size_t)(hd)     * SEQ + s1] = v[0];
                    base[(size_t)(hd + 1) * SEQ + s1] = v[1];
                    float* base2 = vtp + (size_t)((b2 << 4) + h) * HD * SEQ;
                    base2[(size_t)(hd)     * SEQ + s2] = v[2];
                    base2[(size_t)(hd + 1) * SEQ + s2] = v[3];
                } else {          // q/k: [B,H,S,Hd]
                    *(float2*)&Cq[((size_t)((b1 << 4) + h) * SEQ + s1) * HD + hd] = make_float2(v[0], v[1]);
                    *(float2*)&Cq[((size_t)((b2 << 4) + h) * SEQ + s2) * HD + hd] = make_float2(v[2], v[3]);
                }
            }
        }
    }
#undef G_ISSUE
}

// ---------------------------------------------------------------------------
// Flash attention, causal, tf32. BQ=128, BK=64, 256 thr (8 warps x 16 q-rows).
// K and pre-transposed V double-buffered via cp.async; all fragments via
// ldmatrix; P repacked C->A frag by shuffles; ONE barrier per key block.
// ---------------------------------------------------------------------------
#define KST 68
#define ATTN_SMEM ((128 * KST + 4 * 64 * KST) * 4)  // 104448 B
#define NEG_BIG (-1e30f)

__global__ __launch_bounds__(256, 2)
void attn_tf32(const float* __restrict__ q, const float* __restrict__ k,
               const float* __restrict__ vt, float* __restrict__ att)
{
    extern __shared__ unsigned sm[];
    const unsigned sQ = (unsigned)__cvta_generic_to_shared(sm);
    const unsigned sK = sQ + 128 * KST * 4;      // [2][64][KST]
    const unsigned sV = sK + 2 * 64 * KST * 4;   // [2][64][KST]

    const int bh = blockIdx.y;
    const int qb = gridDim.x - 1 - blockIdx.x;   // heavy blocks first
    const int q0 = qb << 7;
    const float* qbase = q  + (size_t)bh * SEQ * HD;
    const float* kbase = k  + (size_t)bh * SEQ * HD;
    const float* vbase = vt + (size_t)bh * HD * SEQ;   // [Hd][S]

    const int tid = threadIdx.x;
    const int warp = tid >> 5, lane = tid & 31;
    const int g = lane >> 2, tg = lane & 3;
    const int rq = warp * 16;
    const unsigned lmo = (unsigned)((((lane & 15) * KST) + ((lane >> 4) << 2)) * 4);

    // Stage Q via cp.async (pre-scaled+rounded in gmem): 8 x 16B per thread
#pragma unroll
    for (int i = 0; i < 8; ++i) {
        const int c = tid + i * 256;
        const int row = c >> 4, col4 = (c & 15) << 2;
        cp16(sQ + (unsigned)((row * KST + col4) * 4),
             qbase + (size_t)(q0 + row) * HD + col4);
    }

#define KV_ISSUE(kb) do { const int buf_ = (kb) & 1;                                   \
    _Pragma("unroll")                                                                  \
    for (int i_ = 0; i_ < 4; ++i_) {                                                   \
        const int c_ = tid + i_ * 256;                                                 \
        const int row_ = c_ >> 4, col_ = (c_ & 15) << 2;                               \
        cp16(sK + (unsigned)(((buf_ * 64 + row_) * KST + col_) * 4),                   \
             kbase + (size_t)(((kb) << 6) + row_) * HD + col_);                        \
        cp16(sV + (unsigned)(((buf_ * 64 + row_) * KST + col_) * 4),                   \
             vbase + (size_t)row_ * SEQ + ((kb) << 6) + col_);                         \
    }                                                                                  \
    CP_COMMIT(); } while (0)

    KV_ISSUE(0);   // commits Q + K/V(0) as one group

    float m_i[2] = {NEG_BIG, NEG_BIG};
    float l_i[2] = {0.f, 0.f};
    float o[8][4] = {};

    const int nkb = 2 * (qb + 1);
    for (int kb = 0; kb < nkb; ++kb) {
        CP_WAIT(0);
        __syncthreads();                 // kb resident; no readers left in buf (kb+1)&1
        if (kb + 1 < nkb) KV_ISSUE(kb + 1);

        const bool active = ((kb << 6) <= q0 + rq + 15);
        if (active) {
            const unsigned bK = sK + (unsigned)((kb & 1) * 64 * KST * 4);
            const unsigned bV = sV + (unsigned)((kb & 1) * 64 * KST * 4);

            // S[16x64] = Q_warp * K^T
            float s[8][4] = {};
#pragma unroll
            for (int ks = 0; ks < 8; ++ks) {
                const int k0 = ks * 8;
                unsigned a0, a1, a2, a3;
                ldsm4(a0, a1, a2, a3, sQ + (unsigned)((rq * KST + k0) * 4) + lmo);
#pragma unroll
                for (int ntp = 0; ntp < 4; ++ntp) {
                    unsigned b0e, b0o, b1e, b1o;
                    ldsm4(b0e, b0o, b1e, b1o,
                          bK + (unsigned)(((ntp * 16) * KST + k0) * 4) + lmo);
                    mma8(s[2 * ntp],     a0, a1, a2, a3, b0e, b1e);
                    mma8(s[2 * ntp + 1], a0, a1, a2, a3, b0o, b1o);
                }
            }

            if ((kb << 6) + 63 > q0 + rq) {   // diagonal block: mask col > row
#pragma unroll
                for (int nt = 0; nt < 8; ++nt)
#pragma unroll
                    for (int j = 0; j < 4; ++j) {
                        const int col = (kb << 6) + nt * 8 + tg * 2 + (j & 1);
                        const int row = q0 + rq + g + 8 * (j >> 1);
                        if (col > row) s[nt][j] = NEG_BIG;
                    }
            }

            // Online softmax per row-half; p kept in registers (tf32 bits)
            unsigned pu[8][4];
#pragma unroll
            for (int h2 = 0; h2 < 2; ++h2) {
                float mx = NEG_BIG;
#pragma unroll
                for (int nt = 0; nt < 8; ++nt)
                    mx = fmaxf(mx, fmaxf(s[nt][2 * h2], s[nt][2 * h2 + 1]));
                mx = fmaxf(mx, __shfl_xor_sync(0xffffffffu, mx, 1));
                mx = fmaxf(mx, __shfl_xor_sync(0xffffffffu, mx, 2));
                const float mnew = fmaxf(m_i[h2], mx);
                const float corr = __expf(m_i[h2] - mnew);
                float rs = 0.f;
#pragma unroll
                for (int nt = 0; nt < 8; ++nt) {
                    float p0 = __expf(s[nt][2 * h2]     - mnew);
                    float p1 = __expf(s[nt][2 * h2 + 1] - mnew);
                    rs += p0 + p1;
                    pu[nt][2 * h2]     = f2tf(p0);
                    pu[nt][2 * h2 + 1] = f2tf(p1);
                }
                rs += __shfl_xor_sync(0xffffffffu, rs, 1);
                rs += __shfl_xor_sync(0xffffffffu, rs, 2);
                m_i[h2] = mnew;
                l_i[h2] = l_i[h2] * corr + rs;
#pragma unroll
                for (int nt = 0; nt < 8; ++nt) {
                    o[nt][2 * h2]     *= corr;
                    o[nt][2 * h2 + 1] *= corr;
                }
            }

            // PV: A-frags by shuffle repack, B-frags by ldmatrix on transposed V
            const int srcA = (g << 2) | (tg >> 1);
            const int srcB = srcA + 2;
            const bool odd = (tg & 1);
#pragma unroll
            for (int ks = 0; ks < 8; ++ks) {
                const int k0 = ks * 8;
                unsigned u0 = __shfl_sync(0xffffffffu, pu[ks][0], srcA);
                unsigned u1 = __shfl_sync(0xffffffffu, pu[ks][1], srcA);
                unsigned u2 = __shfl_sync(0xffffffffu, pu[ks][2], srcA);
                unsigned u3 = __shfl_sync(0xffffffffu, pu[ks][3], srcA);
                unsigned w0 = __shfl_sync(0xffffffffu, pu[ks][0], srcB);
                unsigned w1 = __shfl_sync(0xffffffffu, pu[ks][1], srcB);
                unsigned w2 = __shfl_sync(0xffffffffu, pu[ks][2], srcB);
                unsigned w3 = __shfl_sync(0xffffffffu, pu[ks][3], srcB);
                unsigned a0 = odd ? u1 : u0;
                unsigned a1 = odd ? u3 : u2;
                unsigned a2 = odd ? w1 : w0;
                unsigned a3 = odd ? w3 : w2;
#pragma unroll
                for (int ntp = 0; ntp < 4; ++ntp) {
                    unsigned b0e, b0o, b1e, b1o;
                    ldsm4(b0e, b0o, b1e, b1o,
                          bV + (unsigned)(((ntp * 16) * KST + k0) * 4) + lmo);
                    mma8(o[2 * ntp],     a0, a1, a2, a3, b0e, b1e);
                    mma8(o[2 * ntp + 1], a0, a1, a2, a3, b0o, b1o);
                }
            }
        }
    }

    // Epilogue: [B,S,D] layout, tf32-rounded for the O projection
    const int b = bh >> 4, h = bh & 15;
#pragma unroll
    for (int h2 = 0; h2 < 2; ++h2) {
        const int r = q0 + rq + g + 8 * h2;
        const float inv = 1.0f / l_i[h2];
#pragma unroll
        for (int nt = 0; nt < 8; ++nt) {
            const int d = h * HD + nt * 8 + tg * 2;
            float2 res = make_float2(f2tf_f(o[nt][2 * h2] * inv),
                                     f2tf_f(o[nt][2 * h2 + 1] * inv));
            *(float2*)&att[((size_t)(b * SEQ) + r) * D_MODEL + d] = res;
        }
    }
#undef KV_ISSUE
}

// ---------------------------------------------------------------------------
extern "C" void kernel_launch(void* const* d_in, const int* in_sizes, int n_in,
                              void* d_out, int out_size)
{
    const float* x  = (const float*)d_in[0];
    const float* wq = (const float*)d_in[1];
    const float* wk = (const float*)d_in[2];
    const float* wv = (const float*)d_in[3];
    const float* wo = (const float*)d_in[4];
    float* out = (float*)d_out;

    float *q, *k, *vt, *att, *xt, *wc;
    cudaGetSymbolAddress((void**)&q,   g_q);
    cudaGetSymbolAddress((void**)&k,   g_k);
    cudaGetSymbolAddress((void**)&vt,  g_vt);
    cudaGetSymbolAddress((void**)&att, g_att);
    cudaGetSymbolAddress((void**)&xt,  g_xt);
    cudaGetSymbolAddress((void**)&wc,  g_wc);

    const int NX = M_TOTAL * D_MODEL;      // 8388608
    cvt_rna_kernel<<<NX / 16 / 256, 256>>>(x,  xt,            NX);
    cvt_rna_kernel<<<NW / 16 / 256, 256>>>(wq, wc + 0ul * NW, NW);
    cvt_rna_kernel<<<NW / 16 / 256, 256>>>(wk, wc + 1ul * NW, NW);
    cvt_rna_kernel<<<NW / 16 / 256, 256>>>(wv, wc + 2ul * NW, NW);
    cvt_rna_kernel<<<NW / 16 / 256, 256>>>(wo, wc + 3ul * NW, NW);

    cudaFuncSetAttribute((const void*)gemm_tf32,
                         cudaFuncAttributeMaxDynamicSharedMemorySize, GEMM_SMEM);
    cudaFuncSetAttribute((const void*)attn_tf32,
                         cudaFuncAttributeMaxDynamicSharedMemorySize, ATTN_SMEM);

    // Fused Q/K/Vt projections: z selects weight + epilogue
    dim3 gqkv(D_MODEL / 128, M_TOTAL / 128, 3);
    gemm_tf32<<<gqkv, 256, GEMM_SMEM>>>(xt, wc, q, k, vt, nullptr, -1);

    attn_tf32<<<dim3(SEQ / 128, NB * NHEAD), 256, ATTN_SMEM>>>(q, k, vt, att);

    dim3 go(D_MODEL / 128, M_TOTAL / 128, 1);
    gemm_tf32<<<go, 256, GEMM_SMEM>>>(att, wc, nullptr, nullptr, nullptr, out, 3);
}

// round 12
// speedup vs baseline: 6.7703x; 1.9150x over previous
#include <cuda_runtime.h>
#include <cuda_fp16.h>
#include <cstdint>

#define D_MODEL 1024
#define NHEAD   16
#define HD      64
#define SEQ     2048
#define NB      4
#define M_TOTAL (NB * SEQ)   // 8192
#define NW      (D_MODEL * D_MODEL)

// Scratch (allocation-free rule: __device__ globals) — all fp16 intermediates
__device__ __half g_xh [(size_t)M_TOTAL * D_MODEL];   // fp16 x
__device__ __half g_wh [4][(size_t)NW];               // fp16 weights q,k,v,o
__device__ __half g_qh [(size_t)M_TOTAL * D_MODEL];   // [B,H,S,Hd], pre-scaled 0.125
__device__ __half g_kh [(size_t)M_TOTAL * D_MODEL];   // [B,H,S,Hd]
__device__ __half g_vth[(size_t)M_TOTAL * D_MODEL];   // [B,H,Hd,S] (transposed V)
__device__ __half g_ath[(size_t)M_TOTAL * D_MODEL];   // [B,S,D] attn output

// ---------------------------------------------------------------------------
// Helpers
// ---------------------------------------------------------------------------
__device__ __forceinline__ unsigned packh2(float a, float b) {
    __half2 h = __floats2half2_rn(a, b);      // low = a, high = b
    return *(unsigned*)&h;
}

__device__ __forceinline__ void cp16(unsigned dst, const void* src) {
    asm volatile("cp.async.cg.shared.global [%0], [%1], 16;\n" :: "r"(dst), "l"(src));
}
#define CP_COMMIT() asm volatile("cp.async.commit_group;\n")
#define CP_WAIT(n)  asm volatile("cp.async.wait_group %0;\n" :: "n"(n))

__device__ __forceinline__ void ldsm4(unsigned& r0, unsigned& r1, unsigned& r2, unsigned& r3,
                                      unsigned addr) {
    asm volatile("ldmatrix.sync.aligned.m8n8.x4.shared.b16 {%0,%1,%2,%3}, [%4];"
                 : "=r"(r0), "=r"(r1), "=r"(r2), "=r"(r3) : "r"(addr));
}

// m16n8k16 fp16 mma, f32 accum. (g = lane>>2, tg = lane&3)
//   A: a0={(g,2tg),(g,2tg+1)} a1=rows g+8  a2={(g,2tg+8),...} a3=rows g+8
//   B: b0={(k=2tg,n=g),(k=2tg+1,n=g)} b1=k+8    C: c0=(g,2tg) c1=(g,2tg+1) c2/c3 rows g+8
__device__ __forceinline__ void mma16(float c[4],
                                      unsigned a0, unsigned a1, unsigned a2, unsigned a3,
                                      unsigned b0, unsigned b1) {
    asm volatile(
        "mma.sync.aligned.m16n8k16.row.col.f32.f16.f16.f32 "
        "{%0,%1,%2,%3}, {%4,%5,%6,%7}, {%8,%9}, {%0,%1,%2,%3};"
        : "+f"(c[0]), "+f"(c[1]), "+f"(c[2]), "+f"(c[3])
        : "r"(a0), "r"(a1), "r"(a2), "r"(a3), "r"(b0), "r"(b1));
}

// ---------------------------------------------------------------------------
// Prepass: fp32 -> fp16 (RN)
// ---------------------------------------------------------------------------
__global__ void cvt_f2h(const float* __restrict__ src, __half* __restrict__ dst, int n)
{
    const int base = (blockIdx.x * blockDim.x + threadIdx.x) * 16;
    if (base < n) {
#pragma unroll
        for (int u = 0; u < 4; ++u) {
            float4 v = *(const float4*)(src + base + u * 4);
            *(__half2*)(dst + base + u * 4)     = __floats2half2_rn(v.x, v.y);
            *(__half2*)(dst + base + u * 4 + 2) = __floats2half2_rn(v.z, v.w);
        }
    }
}

// ---------------------------------------------------------------------------
// GEMM: C[M,N] = A[M,K] * W[N,K]^T, fp16 in / f32 accum. 128x128 tile, BK=32,
// 256 thr, 8 warps 2x4 (warp tile 64x32), 3-stage cp.async, ldmatrix frags.
// Smem stride 40 halves (80B: /16=5, 5r mod 8 bijective -> conflict-free).
// mode: 0=q ([B,H,S,Hd] fp16, x0.125)  1=k  2=vt ([B,H,Hd,S] fp16)
//       3=out ([B,S,D] f32).  mode<0 -> blockIdx.z selects weight + epilogue.
// ---------------------------------------------------------------------------
#define GBK   32
#define GSTRB 80                        // bytes per smem row (40 halves)
#define GSTAGE (128 * GSTRB)            // 10240 B per operand
#define GEMM_SMEM (3 * 2 * GSTAGE)      // 61440 B

__global__ __launch_bounds__(256, 2)
void gemm_h(const __half* __restrict__ A, const __half* __restrict__ W4,
            __half* __restrict__ qp, __half* __restrict__ kp,
            __half* __restrict__ vtp, float* __restrict__ op, int mode_in)
{
    extern __shared__ char smem[];
    const unsigned sbase = (unsigned)__cvta_generic_to_shared(smem);
    const int K = D_MODEL;
    const int mode = (mode_in < 0) ? (int)blockIdx.z : mode_in;
    const __half* Bw = W4 + (size_t)mode * NW;

    const int m0 = blockIdx.y << 7;
    const int n0 = blockIdx.x << 7;
    const int tid = threadIdx.x;
    const __half* Ag = A  + (size_t)m0 * K;
    const __half* Bg = Bw + (size_t)n0 * K;

    const int lrw = tid >> 1;            // 0..127 (row for loads)
    const int lc0 = (tid & 1) * 2;       // 16B-chunk base: 0 or 2

#define G_ISSUE(t) do {                                                                \
    const unsigned sa_ = sbase + ((t) % 3) * 2 * GSTAGE;                               \
    const unsigned sb_ = sa_ + GSTAGE;                                                 \
    cp16(sa_ + (unsigned)(lrw * GSTRB + (lc0    ) * 16), Ag + (size_t)lrw * K + (t) * GBK + (lc0    ) * 8); \
    cp16(sa_ + (unsigned)(lrw * GSTRB + (lc0 + 1) * 16), Ag + (size_t)lrw * K + (t) * GBK + (lc0 + 1) * 8); \
    cp16(sb_ + (unsigned)(lrw * GSTRB + (lc0    ) * 16), Bg + (size_t)lrw * K + (t) * GBK + (lc0    ) * 8); \
    cp16(sb_ + (unsigned)(lrw * GSTRB + (lc0 + 1) * 16), Bg + (size_t)lrw * K + (t) * GBK + (lc0 + 1) * 8); \
    CP_COMMIT(); } while (0)

    G_ISSUE(0); G_ISSUE(1);

    const int warp = tid >> 5, lane = tid & 31;
    const int wm = warp >> 2, wn = warp & 3;
    const int g = lane >> 2, tg = lane & 3;
    // A-frag lane offset: row = lane&15, k-half 16B = lane>>4
    const unsigned aoff = (unsigned)((lane & 15) * GSTRB + (lane >> 4) * 16);
    // B-frag lane offset: n-row = (lane&7) + (lane>>4)*8, k-half = (lane>>3)&1
    const unsigned boff = (unsigned)((((lane & 7) + ((lane >> 4) << 3)) * GSTRB) +
                                     (((lane >> 3) & 1) << 4));

    float acc[4][4][4] = {};

    const int NK = K / GBK;  // 32
    for (int t = 0; t < NK; ++t) {
        CP_WAIT(1);
        __syncthreads();                 // tile t resident; stage (t+2)%3 reader-free
        if (t + 2 < NK) G_ISSUE(t + 2);

        const unsigned swA = sbase + (unsigned)((t % 3) * 2 * GSTAGE);
        const unsigned swB = swA + GSTAGE;
#pragma unroll
        for (int kc = 0; kc < 2; ++kc) {
            unsigned af[4][4];
#pragma unroll
            for (int mt = 0; mt < 4; ++mt)
                ldsm4(af[mt][0], af[mt][1], af[mt][2], af[mt][3],
                      swA + (unsigned)((wm * 64 + mt * 16) * GSTRB + kc * 32) + aoff);
#pragma unroll
            for (int np = 0; np < 2; ++np) {
                unsigned r0, r1, r2, r3;
                ldsm4(r0, r1, r2, r3,
                      swB + (unsigned)((wn * 32 + np * 16) * GSTRB + kc * 32) + boff);
#pragma unroll
                for (int mt = 0; mt < 4; ++mt) {
                    mma16(acc[mt][2 * np],     af[mt][0], af[mt][1], af[mt][2], af[mt][3], r0, r1);
                    mma16(acc[mt][2 * np + 1], af[mt][0], af[mt][1], af[mt][2], af[mt][3], r2, r3);
                }
            }
        }
    }

    const float osc = (mode == 0) ? 0.125f : 1.0f;
#pragma unroll
    for (int mt = 0; mt < 4; ++mt) {
#pragma unroll
        for (int nt = 0; nt < 4; ++nt) {
            const int r1 = m0 + wm * 64 + mt * 16 + g;
            const int r2 = r1 + 8;
            const int n  = n0 + wn * 32 + nt * 8 + tg * 2;
            const float* c = acc[mt][nt];
            if (mode == 3) {
                *(float2*)&op[(size_t)r1 * D_MODEL + n] = make_float2(c[0], c[1]);
                *(float2*)&op[(size_t)r2 * D_MODEL + n] = make_float2(c[2], c[3]);
            } else {
                const int h = n >> 6, hd = n & 63;
                const int b1 = r1 >> 11, s1 = r1 & (SEQ - 1);
                const int b2 = r2 >> 11, s2 = r2 & (SEQ - 1);
                if (mode == 2) {          // transposed V: [B,H,Hd,S] fp16
                    __half* base1 = vtp + (size_t)((b1 << 4) + h) * HD * SEQ;
                    __half* base2 = vtp + (size_t)((b2 << 4) + h) * HD * SEQ;
                    base1[(size_t)(hd)     * SEQ + s1] = __float2half_rn(c[0]);
                    base1[(size_t)(hd + 1) * SEQ + s1] = __float2half_rn(c[1]);
                    base2[(size_t)(hd)     * SEQ + s2] = __float2half_rn(c[2]);
                    base2[(size_t)(hd + 1) * SEQ + s2] = __float2half_rn(c[3]);
                } else {                  // q/k: [B,H,S,Hd] fp16
                    __half* dst = (mode == 0) ? qp : kp;
                    *(unsigned*)&dst[((size_t)((b1 << 4) + h) * SEQ + s1) * HD + hd] =
                        packh2(c[0] * osc, c[1] * osc);
                    *(unsigned*)&dst[((size_t)((b2 << 4) + h) * SEQ + s2) * HD + hd] =
                        packh2(c[2] * osc, c[3] * osc);
                }
            }
        }
    }
#undef G_ISSUE
}

// ---------------------------------------------------------------------------
// Flash attention, causal, fp16 mma. BQ=128, BK=64, 256 thr (8 warps x 16 q).
// cp.async double-buffered K/Vt; ldmatrix frags; P goes S->A frag by register
// half2 pack (no shuffles, no smem). Smem stride 72 halves (144B: 9r mod 8 bij).
// ---------------------------------------------------------------------------
#define ASTRB 144                                 // bytes per smem row
#define AQ_BYTES (128 * ASTRB)                    // 18432
#define AK_BYTES (64 * ASTRB)                     // 9216
#define ATTN_SMEM (AQ_BYTES + 4 * AK_BYTES)       // 55296 B
#define NEG_BIG (-1e30f)

__global__ __launch_bounds__(256, 2)
void attn_h(const __half* __restrict__ q, const __half* __restrict__ k,
            const __half* __restrict__ vt, __half* __restrict__ att)
{
    extern __shared__ char smc[];
    const unsigned sQ = (unsigned)__cvta_generic_to_shared(smc);
    const unsigned sK = sQ + AQ_BYTES;            // [2][64][72h]
    const unsigned sV = sK + 2 * AK_BYTES;        // [2][64][72h]

    const int bh = blockIdx.y;
    const int qb = gridDim.x - 1 - blockIdx.x;    // heavy blocks first
    const int q0 = qb << 7;
    const __half* qbase = q  + (size_t)bh * SEQ * HD;
    const __half* kbase = k  + (size_t)bh * SEQ * HD;
    const __half* vbase = vt + (size_t)bh * HD * SEQ;   // [Hd][S]

    const int tid = threadIdx.x;
    const int warp = tid >> 5, lane = tid & 31;
    const int g = lane >> 2, tg = lane & 3;
    const int rq = warp * 16;
    const unsigned aoff = (unsigned)((lane & 15) * ASTRB + (lane >> 4) * 16);
    const unsigned boff = (unsigned)((((lane & 7) + ((lane >> 4) << 3)) * ASTRB) +
                                     (((lane >> 3) & 1) << 4));

    // Stage Q: 128 rows x 64 halves = 1024 x 16B chunks
#pragma unroll
    for (int i = 0; i < 4; ++i) {
        const int c = tid + i * 256;
        const int row = c >> 3, c16 = c & 7;
        cp16(sQ + (unsigned)(row * ASTRB + c16 * 16),
             qbase + (size_t)(q0 + row) * HD + c16 * 8);
    }

#define KV_ISSUE(kb) do { const unsigned bo_ = (unsigned)(((kb) & 1) * AK_BYTES);      \
    _Pragma("unroll")                                                                  \
    for (int i_ = 0; i_ < 2; ++i_) {                                                   \
        const int c_ = tid + i_ * 256;                                                 \
        const int row_ = c_ >> 3, c16_ = c_ & 7;                                       \
        cp16(sK + bo_ + (unsigned)(row_ * ASTRB + c16_ * 16),                          \
             kbase + (size_t)(((kb) << 6) + row_) * HD + c16_ * 8);                    \
        cp16(sV + bo_ + (unsigned)(row_ * ASTRB + c16_ * 16),                          \
             vbase + (size_t)row_ * SEQ + ((kb) << 6) + c16_ * 8);                     \
    }                                                                                  \
    CP_COMMIT(); } while (0)

    KV_ISSUE(0);   // one group: Q + K/V(0)

    float m_i[2] = {NEG_BIG, NEG_BIG};
    float l_i[2] = {0.f, 0.f};
    float o[8][4] = {};

    const int nkb = 2 * (qb + 1);
    for (int kb = 0; kb < nkb; ++kb) {
        CP_WAIT(0);
        __syncthreads();                 // kb resident; other buffer reader-free
        if (kb + 1 < nkb) KV_ISSUE(kb + 1);

        const bool active = ((kb << 6) <= q0 + rq + 15);
        if (active) {
            const unsigned bK = sK + (unsigned)((kb & 1) * AK_BYTES);
            const unsigned bV = sV + (unsigned)((kb & 1) * AK_BYTES);

            // S[16x64] = Q_warp * K^T   (4 k-chunks of 16 x 4 n16-blocks)
            float s[8][4] = {};
#pragma unroll
            for (int kc = 0; kc < 4; ++kc) {
                unsigned a0, a1, a2, a3;
                ldsm4(a0, a1, a2, a3, sQ + (unsigned)(rq * ASTRB + kc * 32) + aoff);
#pragma unroll
                for (int np = 0; np < 4; ++np) {
                    unsigned r0, r1, r2, r3;
                    ldsm4(r0, r1, r2, r3,
                          bK + (unsigned)((np * 16) * ASTRB + kc * 32) + boff);
                    mma16(s[2 * np],     a0, a1, a2, a3, r0, r1);
                    mma16(s[2 * np + 1], a0, a1, a2, a3, r2, r3);
                }
            }

            if ((kb << 6) + 63 > q0 + rq) {   // diagonal block: mask col > row
#pragma unroll
                for (int nt = 0; nt < 8; ++nt)
#pragma unroll
                    for (int j = 0; j < 4; ++j) {
                        const int col = (kb << 6) + nt * 8 + tg * 2 + (j & 1);
                        const int row = q0 + rq + g + 8 * (j >> 1);
                        if (col > row) s[nt][j] = NEG_BIG;
                    }
            }

            // Online softmax per row-half; P packed straight into A-fragments
            unsigned pk[8][2];
#pragma unroll
            for (int h2 = 0; h2 < 2; ++h2) {
                float mx = NEG_BIG;
#pragma unroll
                for (int nt = 0; nt < 8; ++nt)
                    mx = fmaxf(mx, fmaxf(s[nt][2 * h2], s[nt][2 * h2 + 1]));
                mx = fmaxf(mx, __shfl_xor_sync(0xffffffffu, mx, 1));
                mx = fmaxf(mx, __shfl_xor_sync(0xffffffffu, mx, 2));
                const float mnew = fmaxf(m_i[h2], mx);
                const float corr = __expf(m_i[h2] - mnew);
                float rs = 0.f;
#pragma unroll
                for (int nt = 0; nt < 8; ++nt) {
                    float p0 = __expf(s[nt][2 * h2]     - mnew);
                    float p1 = __expf(s[nt][2 * h2 + 1] - mnew);
                    rs += p0 + p1;
                    pk[nt][h2] = packh2(p0, p1);   // = {(row, 2tg), (row, 2tg+1)}
                }
                rs += __shfl_xor_sync(0xffffffffu, rs, 1);
                rs += __shfl_xor_sync(0xffffffffu, rs, 2);
                m_i[h2] = mnew;
                l_i[h2] = l_i[h2] * corr + rs;
#pragma unroll
                for (int nt = 0; nt < 8; ++nt) {
                    o[nt][2 * h2]     *= corr;
                    o[nt][2 * h2 + 1] *= corr;
                }
            }

            // PV: A-frags are pk pairs (C-frag == A-frag pairing for k16 chunks)
#pragma unroll
            for (int kc = 0; kc < 4; ++kc) {
                const unsigned a0 = pk[2 * kc][0],     a1 = pk[2 * kc][1];
                const unsigned a2 = pk[2 * kc + 1][0], a3 = pk[2 * kc + 1][1];
#pragma unroll
                for (int np = 0; np < 4; ++np) {
                    unsigned r0, r1, r2, r3;
                    ldsm4(r0, r1, r2, r3,
                          bV + (unsigned)((np * 16) * ASTRB + kc * 32) + boff);
                    mma16(o[2 * np],     a0, a1, a2, a3, r0, r1);
                    mma16(o[2 * np + 1], a0, a1, a2, a3, r2, r3);
                }
            }
        }
    }

    // Epilogue: [B,S,D] fp16 for the O projection
    const int b = bh >> 4, h = bh & 15;
#pragma unroll
    for (int h2 = 0; h2 < 2; ++h2) {
        const int r = q0 + rq + g + 8 * h2;
        const float inv = 1.0f / l_i[h2];
#pragma unroll
        for (int nt = 0; nt < 8; ++nt) {
            const int d = h * HD + nt * 8 + tg * 2;
            *(unsigned*)&att[((size_t)(b * SEQ) + r) * D_MODEL + d] =
                packh2(o[nt][2 * h2] * inv, o[nt][2 * h2 + 1] * inv);
        }
    }
#undef KV_ISSUE
}

// ---------------------------------------------------------------------------
extern "C" void kernel_launch(void* const* d_in, const int* in_sizes, int n_in,
                              void* d_out, int out_size)
{
    const float* x  = (const float*)d_in[0];
    const float* wq = (const float*)d_in[1];
    const float* wk = (const float*)d_in[2];
    const float* wv = (const float*)d_in[3];
    const float* wo = (const float*)d_in[4];
    float* out = (float*)d_out;

    __half *xh, *wh, *qh, *kh, *vth, *ath;
    cudaGetSymbolAddress((void**)&xh,  g_xh);
    cudaGetSymbolAddress((void**)&wh,  g_wh);
    cudaGetSymbolAddress((void**)&qh,  g_qh);
    cudaGetSymbolAddress((void**)&kh,  g_kh);
    cudaGetSymbolAddress((void**)&vth, g_vth);
    cudaGetSymbolAddress((void**)&ath, g_ath);

    const int NX = M_TOTAL * D_MODEL;
    cvt_f2h<<<NX / 16 / 256, 256>>>(x,  xh,            NX);
    cvt_f2h<<<NW / 16 / 256, 256>>>(wq, wh + 0ul * NW, NW);
    cvt_f2h<<<NW / 16 / 256, 256>>>(wk, wh + 1ul * NW, NW);
    cvt_f2h<<<NW / 16 / 256, 256>>>(wv, wh + 2ul * NW, NW);
    cvt_f2h<<<NW / 16 / 256, 256>>>(wo, wh + 3ul * NW, NW);

    cudaFuncSetAttribute((const void*)gemm_h,
                         cudaFuncAttributeMaxDynamicSharedMemorySize, GEMM_SMEM);
    cudaFuncSetAttribute((const void*)attn_h,
                         cudaFuncAttributeMaxDynamicSharedMemorySize, ATTN_SMEM);

    // Fused Q/K/Vt projections (z selects weight + epilogue)
    dim3 gqkv(D_MODEL / 128, M_TOTAL / 128, 3);
    gemm_h<<<gqkv, 256, GEMM_SMEM>>>(xh, wh, qh, kh, vth, nullptr, -1);

    attn_h<<<dim3(SEQ / 128, NB * NHEAD), 256, ATTN_SMEM>>>(qh, kh, vth, ath);

    dim3 go(D_MODEL / 128, M_TOTAL / 128, 1);
    gemm_h<<<go, 256, GEMM_SMEM>>>(ath, wh, nullptr, nullptr, nullptr, out, 3);
}

// round 17
// speedup vs baseline: 7.6752x; 1.1336x over previous
#include <cuda_runtime.h>
#include <cuda_fp16.h>
#include <cstdint>

#define D_MODEL 1024
#define NHEAD   16
#define HD      64
#define SEQ     2048
#define NB      4
#define M_TOTAL (NB * SEQ)   // 8192
#define NW      (D_MODEL * D_MODEL)

// Scratch (allocation-free rule: __device__ globals) — all fp16 intermediates
__device__ __half g_xh [(size_t)M_TOTAL * D_MODEL];   // fp16 x
__device__ __half g_wh [4][(size_t)NW];               // fp16 weights q,k,v,o
__device__ __half g_qh [(size_t)M_TOTAL * D_MODEL];   // [B,H,S,Hd], x (0.125*log2e)
__device__ __half g_kh [(size_t)M_TOTAL * D_MODEL];   // [B,H,S,Hd]
__device__ __half g_vth[(size_t)M_TOTAL * D_MODEL];   // [B,H,Hd,S] (transposed V)
__device__ __half g_ath[(size_t)M_TOTAL * D_MODEL];   // [B,S,D] attn output

// ---------------------------------------------------------------------------
// Helpers
// ---------------------------------------------------------------------------
__device__ __forceinline__ unsigned packh2(float a, float b) {
    __half2 h = __floats2half2_rn(a, b);      // low = a, high = b
    return *(unsigned*)&h;
}

__device__ __forceinline__ void cp16(unsigned dst, const void* src) {
    asm volatile("cp.async.cg.shared.global [%0], [%1], 16;\n" :: "r"(dst), "l"(src));
}
#define CP_COMMIT() asm volatile("cp.async.commit_group;\n")
#define CP_WAIT(n)  asm volatile("cp.async.wait_group %0;\n" :: "n"(n))

__device__ __forceinline__ void ldsm4(unsigned& r0, unsigned& r1, unsigned& r2, unsigned& r3,
                                      unsigned addr) {
    asm volatile("ldmatrix.sync.aligned.m8n8.x4.shared.b16 {%0,%1,%2,%3}, [%4];"
                 : "=r"(r0), "=r"(r1), "=r"(r2), "=r"(r3) : "r"(addr));
}

// m16n8k16 fp16 mma, f32 accum. (g = lane>>2, tg = lane&3)
__device__ __forceinline__ void mma16(float c[4],
                                      unsigned a0, unsigned a1, unsigned a2, unsigned a3,
                                      unsigned b0, unsigned b1) {
    asm volatile(
        "mma.sync.aligned.m16n8k16.row.col.f32.f16.f16.f32 "
        "{%0,%1,%2,%3}, {%4,%5,%6,%7}, {%8,%9}, {%0,%1,%2,%3};"
        : "+f"(c[0]), "+f"(c[1]), "+f"(c[2]), "+f"(c[3])
        : "r"(a0), "r"(a1), "r"(a2), "r"(a3), "r"(b0), "r"(b1));
}

// ---------------------------------------------------------------------------
// Prepass: fp32 -> fp16 (RN). Plain variant for x; 4-way variant for weights.
// ---------------------------------------------------------------------------
__device__ __forceinline__ void cvt16(const float* __restrict__ src,
                                      __half* __restrict__ dst, int base) {
#pragma unroll
    for (int u = 0; u < 4; ++u) {
        float4 v = *(const float4*)(src + base + u * 4);
        *(__half2*)(dst + base + u * 4)     = __floats2half2_rn(v.x, v.y);
        *(__half2*)(dst + base + u * 4 + 2) = __floats2half2_rn(v.z, v.w);
    }
}

__global__ void cvt_f2h(const float* __restrict__ src, __half* __restrict__ dst, int n)
{
    const int base = (blockIdx.x * blockDim.x + threadIdx.x) * 16;
    if (base < n) cvt16(src, dst, base);
}

__global__ void cvt_f2h_w(const float* __restrict__ w0, const float* __restrict__ w1,
                          const float* __restrict__ w2, const float* __restrict__ w3,
                          __half* __restrict__ dst)
{
    const int base = (blockIdx.x * blockDim.x + threadIdx.x) * 16;
    const float* src = (blockIdx.y == 0) ? w0 : (blockIdx.y == 1) ? w1
                     : (blockIdx.y == 2) ? w2 : w3;
    cvt16(src, dst + (size_t)blockIdx.y * NW, base);
}

// ---------------------------------------------------------------------------
// GEMM: C[M,N] = A[M,K] * W[N,K]^T, fp16 in / f32 accum. 128x128 tile, BK=64,
// 256 thr, 8 warps 2x4 (warp tile 64x32), 3-stage cp.async, ldmatrix frags.
// Smem row pitch 144 B (72 halves: 9*16B chunks, 9r mod 8 bijective).
// mode: 0=q ([B,H,S,Hd] fp16, x 0.125*log2e)  1=k  2=vt ([B,H,Hd,S] fp16)
//       3=out ([B,S,D] f32).  mode<0 -> blockIdx.z selects weight + epilogue.
// ---------------------------------------------------------------------------
#define GBK    64
#define GSTRB  144                       // bytes per smem row (72 halves)
#define GSTAGE (128 * GSTRB)             // 18432 B per operand
#define GEMM_SMEM (3 * 2 * GSTAGE)       // 110592 B (2 CTAs/SM: 216KB <= 228KB)
#define QSCALE (0.125f * 1.4426950408889634f)   // 1/sqrt(64) * log2(e)

__global__ __launch_bounds__(256, 2)
void gemm_h(const __half* __restrict__ A, const __half* __restrict__ W4,
            __half* __restrict__ qp, __half* __restrict__ kp,
            __half* __restrict__ vtp, float* __restrict__ op, int mode_in)
{
    extern __shared__ char smem[];
    const unsigned sbase = (unsigned)__cvta_generic_to_shared(smem);
    const int K = D_MODEL;
    const int mode = (mode_in < 0) ? (int)blockIdx.z : mode_in;
    const __half* Bw = W4 + (size_t)mode * NW;

    const int m0 = blockIdx.y << 7;
    const int n0 = blockIdx.x << 7;
    const int tid = threadIdx.x;
    const __half* Ag = A  + (size_t)m0 * K;
    const __half* Bg = Bw + (size_t)n0 * K;

    // 128 rows x 128B per operand per tile = 1024 x 16B chunks -> 4/thread
#define G_ISSUE(t) do {                                                                \
    const unsigned sa_ = sbase + ((t) % 3) * 2 * GSTAGE;                               \
    const unsigned sb_ = sa_ + GSTAGE;                                                 \
    _Pragma("unroll")                                                                  \
    for (int i_ = 0; i_ < 4; ++i_) {                                                   \
        const int c_ = tid + i_ * 256;                                                 \
        const int row_ = c_ >> 3, c16_ = c_ & 7;                                       \
        cp16(sa_ + (unsigned)(row_ * GSTRB + c16_ * 16),                               \
             Ag + (size_t)row_ * K + (t) * GBK + c16_ * 8);                            \
        cp16(sb_ + (unsigned)(row_ * GSTRB + c16_ * 16),                               \
             Bg + (size_t)row_ * K + (t) * GBK + c16_ * 8);                            \
    }                                                                                  \
    CP_COMMIT(); } while (0)

    G_ISSUE(0); G_ISSUE(1);

    const int warp = tid >> 5, lane = tid & 31;
    const int wm = warp >> 2, wn = warp & 3;
    const int g = lane >> 2, tg = lane & 3;
    const unsigned aoff = (unsigned)((lane & 15) * GSTRB + (lane >> 4) * 16);
    const unsigned boff = (unsigned)((((lane & 7) + ((lane >> 4) << 3)) * GSTRB) +
                                     (((lane >> 3) & 1) << 4));

    float acc[4][4][4] = {};

    const int NK = K / GBK;  // 16
    for (int t = 0; t < NK; ++t) {
        if (t + 1 < NK) { CP_WAIT(1); } else { CP_WAIT(0); }  // last tile: full drain
        __syncthreads();                  // tile t resident; stage (t+2)%3 reader-free
        if (t + 2 < NK) G_ISSUE(t + 2);

        const unsigned swA = sbase + (unsigned)((t % 3) * 2 * GSTAGE);
        const unsigned swB = swA + GSTAGE;
#pragma unroll
        for (int kc = 0; kc < 4; ++kc) {
            unsigned af[4][4];
#pragma unroll
            for (int mt = 0; mt < 4; ++mt)
                ldsm4(af[mt][0], af[mt][1], af[mt][2], af[mt][3],
                      swA + (unsigned)((wm * 64 + mt * 16) * GSTRB + kc * 32) + aoff);
#pragma unroll
            for (int np = 0; np < 2; ++np) {
                unsigned r0, r1, r2, r3;
                ldsm4(r0, r1, r2, r3,
                      swB + (unsigned)((wn * 32 + np * 16) * GSTRB + kc * 32) + boff);
#pragma unroll
                for (int mt = 0; mt < 4; ++mt) {
                    mma16(acc[mt][2 * np],     af[mt][0], af[mt][1], af[mt][2], af[mt][3], r0, r1);
                    mma16(acc[mt][2 * np + 1], af[mt][0], af[mt][1], af[mt][2], af[mt][3], r2, r3);
                }
            }
        }
    }

    const float osc = (mode == 0) ? QSCALE : 1.0f;
#pragma unroll
    for (int mt = 0; mt < 4; ++mt) {
#pragma unroll
        for (int nt = 0; nt < 4; ++nt) {
            const int r1 = m0 + wm * 64 + mt * 16 + g;
            const int r2 = r1 + 8;
            const int n  = n0 + wn * 32 + nt * 8 + tg * 2;
            const float* c = acc[mt][nt];
            if (mode == 3) {
                *(float2*)&op[(size_t)r1 * D_MODEL + n] = make_float2(c[0], c[1]);
                *(float2*)&op[(size_t)r2 * D_MODEL + n] = make_float2(c[2], c[3]);
            } else {
                const int h = n >> 6, hd = n & 63;
                const int b1 = r1 >> 11, s1 = r1 & (SEQ - 1);
                const int b2 = r2 >> 11, s2 = r2 & (SEQ - 1);
                if (mode == 2) {          // transposed V: [B,H,Hd,S] fp16
                    __half* base1 = vtp + (size_t)((b1 << 4) + h) * HD * SEQ;
                    __half* base2 = vtp + (size_t)((b2 << 4) + h) * HD * SEQ;
                    base1[(size_t)(hd)     * SEQ + s1] = __float2half_rn(c[0]);
                    base1[(size_t)(hd + 1) * SEQ + s1] = __float2half_rn(c[1]);
                    base2[(size_t)(hd)     * SEQ + s2] = __float2half_rn(c[2]);
                    base2[(size_t)(hd + 1) * SEQ + s2] = __float2half_rn(c[3]);
                } else {                  // q/k: [B,H,S,Hd] fp16
                    __half* dst = (mode == 0) ? qp : kp;
                    *(unsigned*)&dst[((size_t)((b1 << 4) + h) * SEQ + s1) * HD + hd] =
                        packh2(c[0] * osc, c[1] * osc);
                    *(unsigned*)&dst[((size_t)((b2 << 4) + h) * SEQ + s2) * HD + hd] =
                        packh2(c[2] * osc, c[3] * osc);
                }
            }
        }
    }
#undef G_ISSUE
}

// ---------------------------------------------------------------------------
// Flash attention, causal, fp16 mma, exp2-domain softmax (Q pre-scaled by
// 0.125*log2e so MUFU.EX2 needs no multiply). BQ=128, BK=64, 256 thr.
// cp.async double-buffered K/Vt; ldmatrix frags; P packed S->A in registers.
// ---------------------------------------------------------------------------
#define ASTRB 144                                 // bytes per smem row
#define AQ_BYTES (128 * ASTRB)                    // 18432
#define AK_BYTES (64 * ASTRB)                     // 9216
#define ATTN_SMEM (AQ_BYTES + 4 * AK_BYTES)       // 55296 B
#define NEG_BIG (-1e30f)

__global__ __launch_bounds__(256, 2)
void attn_h(const __half* __restrict__ q, const __half* __restrict__ k,
            const __half* __restrict__ vt, __half* __restrict__ att)
{
    extern __shared__ char smc[];
    const unsigned sQ = (unsigned)__cvta_generic_to_shared(smc);
    const unsigned sK = sQ + AQ_BYTES;            // [2][64][72h]
    const unsigned sV = sK + 2 * AK_BYTES;        // [2][64][72h]

    const int bh = blockIdx.y;
    const int qb = gridDim.x - 1 - blockIdx.x;    // heavy blocks first
    const int q0 = qb << 7;
    const __half* qbase = q  + (size_t)bh * SEQ * HD;
    const __half* kbase = k  + (size_t)bh * SEQ * HD;
    const __half* vbase = vt + (size_t)bh * HD * SEQ;   // [Hd][S]

    const int tid = threadIdx.x;
    const int warp = tid >> 5, lane = tid & 31;
    const int g = lane >> 2, tg = lane & 3;
    const int rq = warp * 16;
    const unsigned aoff = (unsigned)((lane & 15) * ASTRB + (lane >> 4) * 16);
    const unsigned boff = (unsigned)((((lane & 7) + ((lane >> 4) << 3)) * ASTRB) +
                                     (((lane >> 3) & 1) << 4));

#pragma unroll
    for (int i = 0; i < 4; ++i) {
        const int c = tid + i * 256;
        const int row = c >> 3, c16 = c & 7;
        cp16(sQ + (unsigned)(row * ASTRB + c16 * 16),
             qbase + (size_t)(q0 + row) * HD + c16 * 8);
    }

#define KV_ISSUE(kb) do { const unsigned bo_ = (unsigned)(((kb) & 1) * AK_BYTES);      \
    _Pragma("unroll")                                                                  \
    for (int i_ = 0; i_ < 2; ++i_) {                                                   \
        const int c_ = tid + i_ * 256;                                                 \
        const int row_ = c_ >> 3, c16_ = c_ & 7;                                       \
        cp16(sK + bo_ + (unsigned)(row_ * ASTRB + c16_ * 16),                          \
             kbase + (size_t)(((kb) << 6) + row_) * HD + c16_ * 8);                    \
        cp16(sV + bo_ + (unsigned)(row_ * ASTRB + c16_ * 16),                          \
             vbase + (size_t)row_ * SEQ + ((kb) << 6) + c16_ * 8);                     \
    }                                                                                  \
    CP_COMMIT(); } while (0)

    KV_ISSUE(0);   // one group: Q + K/V(0)

    float m_i[2] = {NEG_BIG, NEG_BIG};
    float l_i[2] = {0.f, 0.f};
    float o[8][4] = {};

    const int nkb = 2 * (qb + 1);
    for (int kb = 0; kb < nkb; ++kb) {
        CP_WAIT(0);
        __syncthreads();                 // kb resident; other buffer reader-free
        if (kb + 1 < nkb) KV_ISSUE(kb + 1);

        const bool active = ((kb << 6) <= q0 + rq + 15);
        if (active) {
            const unsigned bK = sK + (unsigned)((kb & 1) * AK_BYTES);
            const unsigned bV = sV + (unsigned)((kb & 1) * AK_BYTES);

            // S[16x64] = Q_warp * K^T  (log2-domain scores)
            float s[8][4] = {};
#pragma unroll
            for (int kc = 0; kc < 4; ++kc) {
                unsigned a0, a1, a2, a3;
                ldsm4(a0, a1, a2, a3, sQ + (unsigned)(rq * ASTRB + kc * 32) + aoff);
#pragma unroll
                for (int np = 0; np < 4; ++np) {
                    unsigned r0, r1, r2, r3;
                    ldsm4(r0, r1, r2, r3,
                          bK + (unsigned)((np * 16) * ASTRB + kc * 32) + boff);
                    mma16(s[2 * np],     a0, a1, a2, a3, r0, r1);
                    mma16(s[2 * np + 1], a0, a1, a2, a3, r2, r3);
                }
            }

            if ((kb << 6) + 63 > q0 + rq) {   // diagonal block: mask col > row
#pragma unroll
                for (int nt = 0; nt < 8; ++nt)
#pragma unroll
                    for (int j = 0; j < 4; ++j) {
                        const int col = (kb << 6) + nt * 8 + tg * 2 + (j & 1);
                        const int row = q0 + rq + g + 8 * (j >> 1);
                        if (col > row) s[nt][j] = NEG_BIG;
                    }
            }

            // Online softmax per row-half (base-2); P packed into A-fragments
            unsigned pk[8][2];
#pragma unroll
            for (int h2 = 0; h2 < 2; ++h2) {
                float mx = NEG_BIG;
#pragma unroll
                for (int nt = 0; nt < 8; ++nt)
                    mx = fmaxf(mx, fmaxf(s[nt][2 * h2], s[nt][2 * h2 + 1]));
                mx = fmaxf(mx, __shfl_xor_sync(0xffffffffu, mx, 1));
                mx = fmaxf(mx, __shfl_xor_sync(0xffffffffu, mx, 2));
                const float mnew = fmaxf(m_i[h2], mx);
                const float corr = exp2f(m_i[h2] - mnew);
                float rs = 0.f;
#pragma unroll
                for (int nt = 0; nt < 8; ++nt) {
                    float p0 = exp2f(s[nt][2 * h2]     - mnew);
                    float p1 = exp2f(s[nt][2 * h2 + 1] - mnew);
                    rs += p0 + p1;
                    pk[nt][h2] = packh2(p0, p1);
                }
                rs += __shfl_xor_sync(0xffffffffu, rs, 1);
                rs += __shfl_xor_sync(0xffffffffu, rs, 2);
                m_i[h2] = mnew;
                l_i[h2] = l_i[h2] * corr + rs;
#pragma unroll
                for (int nt = 0; nt < 8; ++nt) {
                    o[nt][2 * h2]     *= corr;
                    o[nt][2 * h2 + 1] *= corr;
                }
            }

            // PV: A-frags are pk pairs (C-frag == A-frag pairing for k16 chunks)
#pragma unroll
            for (int kc = 0; kc < 4; ++kc) {
                const unsigned a0 = pk[2 * kc][0],     a1 = pk[2 * kc][1];
                const unsigned a2 = pk[2 * kc + 1][0], a3 = pk[2 * kc + 1][1];
#pragma unroll
                for (int np = 0; np < 4; ++np) {
                    unsigned r0, r1, r2, r3;
                    ldsm4(r0, r1, r2, r3,
                          bV + (unsigned)((np * 16) * ASTRB + kc * 32) + boff);
                    mma16(o[2 * np],     a0, a1, a2, a3, r0, r1);
                    mma16(o[2 * np + 1], a0, a1, a2, a3, r2, r3);
                }
            }
        }
    }

    // Epilogue: [B,S,D] fp16 for the O projection
    const int b = bh >> 4, h = bh & 15;
#pragma unroll
    for (int h2 = 0; h2 < 2; ++h2) {
        const int r = q0 + rq + g + 8 * h2;
        const float inv = 1.0f / l_i[h2];
#pragma unroll
        for (int nt = 0; nt < 8; ++nt) {
            const int d = h * HD + nt * 8 + tg * 2;
            *(unsigned*)&att[((size_t)(b * SEQ) + r) * D_MODEL + d] =
                packh2(o[nt][2 * h2] * inv, o[nt][2 * h2 + 1] * inv);
        }
    }
#undef KV_ISSUE
}

// ---------------------------------------------------------------------------
extern "C" void kernel_launch(void* const* d_in, const int* in_sizes, int n_in,
                              void* d_out, int out_size)
{
    const float* x  = (const float*)d_in[0];
    const float* wq = (const float*)d_in[1];
    const float* wk = (const float*)d_in[2];
    const float* wv = (const float*)d_in[3];
    const float* wo = (const float*)d_in[4];
    float* out = (float*)d_out;

    __half *xh, *wh, *qh, *kh, *vth, *ath;
    cudaGetSymbolAddress((void**)&xh,  g_xh);
    cudaGetSymbolAddress((void**)&wh,  g_wh);
    cudaGetSymbolAddress((void**)&qh,  g_qh);
    cudaGetSymbolAddress((void**)&kh,  g_kh);
    cudaGetSymbolAddress((void**)&vth, g_vth);
    cudaGetSymbolAddress((void**)&ath, g_ath);

    const int NX = M_TOTAL * D_MODEL;
    cvt_f2h<<<NX / 16 / 256, 256>>>(x, xh, NX);
    cvt_f2h_w<<<dim3(NW / 16 / 256, 4), 256>>>(wq, wk, wv, wo, wh);

    cudaFuncSetAttribute((const void*)gemm_h,
                         cudaFuncAttributeMaxDynamicSharedMemorySize, GEMM_SMEM);
    cudaFuncSetAttribute((const void*)attn_h,
                         cudaFuncAttributeMaxDynamicSharedMemorySize, ATTN_SMEM);

    // Fused Q/K/Vt projections (z selects weight + epilogue)
    dim3 gqkv(D_MODEL / 128, M_TOTAL / 128, 3);
    gemm_h<<<gqkv, 256, GEMM_SMEM>>>(xh, wh, qh, kh, vth, nullptr, -1);

    attn_h<<<dim3(SEQ / 128, NB * NHEAD), 256, ATTN_SMEM>>>(qh, kh, vth, ath);

    dim3 go(D_MODEL / 128, M_TOTAL / 128, 1);
    gemm_h<<<go, 256, GEMM_SMEM>>>(ath, wh, nullptr, nullptr, nullptr, out, 3);
}